// round 1
// baseline (speedup 1.0000x reference)
#include <cuda_runtime.h>
#include <math.h>

#define SEQ   1024
#define DM    1024
#define HN    16
#define HDIM  64
#define NSAMP 8
#define INTER 768
#define BATCH 4
#define EPS   1e-5f

// ---------------- scratch (device globals; no allocations allowed) ----------
__device__ float g_hsmean[BATCH * DM];
__device__ float g_partial[BATCH * 16 * DM];
__device__ int   g_expert[NSAMP];
__device__ float g_w[NSAMP];
__device__ float g_qkv[(size_t)NSAMP * SEQ * 3 * DM];        // 96 MB
__device__ float g_scores[(size_t)NSAMP * HN * SEQ * SEQ];   // 512 MB
__device__ float g_ctx[(size_t)NSAMP * SEQ * DM];            // 32 MB
__device__ float g_ao[(size_t)NSAMP * SEQ * DM];             // 32 MB
__device__ float g_x1[(size_t)NSAMP * SEQ * DM];             // 32 MB
__device__ float g_gu[(size_t)NSAMP * SEQ * 2 * INTER];      // 48 MB
__device__ float g_act[(size_t)NSAMP * SEQ * INTER];         // 24 MB
__device__ float g_mlp[(size_t)NSAMP * SEQ * DM];            // 32 MB

// ---------------- helpers ----------------------------------------------------
__device__ __forceinline__ float block_reduce_sum(float v, float* sh) {
    int tid = threadIdx.x;
    #pragma unroll
    for (int o = 16; o; o >>= 1) v += __shfl_down_sync(0xFFFFFFFFu, v, o);
    if ((tid & 31) == 0) sh[tid >> 5] = v;
    __syncthreads();
    float r = 0.f;
    if (tid < 32) {
        float x = (tid < (int)(blockDim.x >> 5)) ? sh[tid] : 0.f;
        #pragma unroll
        for (int o = 16; o; o >>= 1) x += __shfl_down_sync(0xFFFFFFFFu, x, o);
        if (tid == 0) sh[0] = x;
    }
    __syncthreads();
    r = sh[0];
    __syncthreads();
    return r;
}

__device__ __forceinline__ float block_reduce_max(float v, float* sh) {
    int tid = threadIdx.x;
    #pragma unroll
    for (int o = 16; o; o >>= 1) v = fmaxf(v, __shfl_down_sync(0xFFFFFFFFu, v, o));
    if ((tid & 31) == 0) sh[tid >> 5] = v;
    __syncthreads();
    float r;
    if (tid < 32) {
        float x = (tid < (int)(blockDim.x >> 5)) ? sh[tid] : -INFINITY;
        #pragma unroll
        for (int o = 16; o; o >>= 1) x = fmaxf(x, __shfl_down_sync(0xFFFFFFFFu, x, o));
        if (tid == 0) sh[0] = x;
    }
    __syncthreads();
    r = sh[0];
    __syncthreads();
    return r;
}

// ---------------- routing ----------------------------------------------------
// stage 1: partial sums over 64-seq chunks, coalesced over d
__global__ void mean1_kernel(const float* __restrict__ hidden) {
    int b = blockIdx.x, c = blockIdx.y;      // 4 x 16
    int tid = threadIdx.x;                    // 256
    float acc[4] = {0.f, 0.f, 0.f, 0.f};
    for (int s = c * 64; s < c * 64 + 64; s++) {
        const float* row = hidden + ((size_t)b * SEQ + s) * DM;
        #pragma unroll
        for (int i = 0; i < 4; i++) acc[i] += row[tid + i * 256];
    }
    #pragma unroll
    for (int i = 0; i < 4; i++)
        g_partial[((size_t)b * 16 + c) * DM + tid + i * 256] = acc[i];
}

__global__ void mean2_kernel() {
    int b = blockIdx.x;
    int tid = threadIdx.x; // 256
    #pragma unroll
    for (int i = 0; i < 4; i++) {
        int d = tid + i * 256;
        float s = 0.f;
        for (int c = 0; c < 16; c++) s += g_partial[((size_t)b * 16 + c) * DM + d];
        g_hsmean[b * DM + d] = s * (1.0f / (float)SEQ);
    }
}

__global__ void routing_kernel(const float* __restrict__ Wr,
                               const float* __restrict__ temperature,
                               float* __restrict__ out_logits) {
    int tid = threadIdx.x;          // 1024
    int w = tid >> 5, lane = tid & 31;
    int b = w >> 3, c = w & 7;      // 4 batches x 8 cols = 32 warps
    float s = 0.f;
    for (int d = lane; d < DM; d += 32)
        s += g_hsmean[b * DM + d] * Wr[c * DM + d];
    #pragma unroll
    for (int o = 16; o; o >>= 1) s += __shfl_down_sync(0xFFFFFFFFu, s, o);
    __shared__ float logits[32];
    if (lane == 0) logits[w] = s;
    __syncthreads();
    if (tid < BATCH) {
        float t = fminf(fmaxf(temperature[0], 0.1f), 10.0f);
        float lv[8];
        #pragma unroll
        for (int cc = 0; cc < 8; cc++) {
            lv[cc] = logits[tid * 8 + cc] / t;
            out_logits[tid * 8 + cc] = lv[cc];
        }
        // top-2 (first occurrence on ties, matching jax.lax.top_k)
        int i0 = 0;
        #pragma unroll
        for (int cc = 1; cc < 8; cc++) if (lv[cc] > lv[i0]) i0 = cc;
        int i1 = -1;
        #pragma unroll
        for (int cc = 0; cc < 8; cc++) {
            if (cc == i0) continue;
            if (i1 < 0 || lv[cc] > lv[i1]) i1 = cc;
        }
        float e = expf(lv[i1] - lv[i0]);
        float w0 = 1.0f / (1.0f + e);
        float w1 = e / (1.0f + e);
        g_expert[2 * tid]     = i0;
        g_expert[2 * tid + 1] = i1;
        g_w[2 * tid]     = w0;
        g_w[2 * tid + 1] = w1;
    }
}

// ---------------- generic expert SGEMM: C[n] = A[n] @ W[expert[n]] ----------
// M=1024 rows, lda = K, ldb = N, ldc = N. All dims: M%128==0, N%128==0, K%8==0.
#define BM 128
#define BN 128
#define BKK 8
#define TM 8
#define TN 8

__global__ __launch_bounds__(256) void sgemm_kernel(
    const float* __restrict__ Abase, const float* __restrict__ Bbase,
    float* __restrict__ Cbase, int M, int N, int K, int a_div2)
{
    int ns = blockIdx.z;
    const float* A = Abase + (size_t)(a_div2 ? (ns >> 1) : ns) * M * K;
    const float* B = Bbase + (size_t)g_expert[ns] * K * N;
    float* C = Cbase + (size_t)ns * M * N;

    __shared__ float As[BKK][BM];
    __shared__ float Bs[BKK][BN];

    int tid = threadIdx.x;
    int row0 = blockIdx.y * BM;
    int col0 = blockIdx.x * BN;

    int a_r = tid >> 1;            // 0..127
    int a_c = (tid & 1) * 4;       // 0 or 4
    int b_r = tid >> 5;            // 0..7
    int b_c = (tid & 31) * 4;      // 0..124

    int ty = tid >> 4;             // 0..15
    int tx = tid & 15;

    float acc[TM][TN];
    #pragma unroll
    for (int i = 0; i < TM; i++)
        #pragma unroll
        for (int j = 0; j < TN; j++) acc[i][j] = 0.f;

    for (int k0 = 0; k0 < K; k0 += BKK) {
        float4 av = *(const float4*)(A + (size_t)(row0 + a_r) * K + k0 + a_c);
        As[a_c + 0][a_r] = av.x;
        As[a_c + 1][a_r] = av.y;
        As[a_c + 2][a_r] = av.z;
        As[a_c + 3][a_r] = av.w;
        float4 bv = *(const float4*)(B + (size_t)(k0 + b_r) * N + col0 + b_c);
        *(float4*)&Bs[b_r][b_c] = bv;
        __syncthreads();
        #pragma unroll
        for (int k = 0; k < BKK; k++) {
            float ar[TM], br[TN];
            #pragma unroll
            for (int i = 0; i < TM; i += 4) *(float4*)&ar[i] = *(float4*)&As[k][ty * TM + i];
            #pragma unroll
            for (int j = 0; j < TN; j += 4) *(float4*)&br[j] = *(float4*)&Bs[k][tx * TN + j];
            #pragma unroll
            for (int i = 0; i < TM; i++)
                #pragma unroll
                for (int j = 0; j < TN; j++)
                    acc[i][j] = fmaf(ar[i], br[j], acc[i][j]);
        }
        __syncthreads();
    }
    #pragma unroll
    for (int i = 0; i < TM; i++) {
        float* crow = C + (size_t)(row0 + ty * TM + i) * N + col0 + tx * TN;
        #pragma unroll
        for (int j = 0; j < TN; j += 4) {
            float4 v = make_float4(acc[i][j], acc[i][j + 1], acc[i][j + 2], acc[i][j + 3]);
            *(float4*)(crow + j) = v;
        }
    }
}

// ---------------- RoPE (in-place on q,k inside g_qkv) ------------------------
__global__ void rope_kernel(const float* __restrict__ cosb, const float* __restrict__ sinb) {
    int s = blockIdx.x, n = blockIdx.y;
    int tid = threadIdx.x;            // 512
    int h = tid >> 5, j = tid & 31;
    float c0 = cosb[s * HDIM + j],      s0 = sinb[s * HDIM + j];
    float c1 = cosb[s * HDIM + j + 32], s1 = sinb[s * HDIM + j + 32];
    float* row = g_qkv + ((size_t)n * SEQ + s) * (3 * DM);
    float* q = row + h * HDIM;
    float qa = q[j], qb = q[j + 32];
    q[j]      = qa * c0 - qb * s0;
    q[j + 32] = qb * c1 + qa * s1;
    float* k = row + DM + h * HDIM;
    float ka = k[j], kb = k[j + 32];
    k[j]      = ka * c0 - kb * s0;
    k[j + 32] = kb * c1 + ka * s1;
}

// ---------------- attention scores: S = Q K^T / 8 ----------------------------
__global__ __launch_bounds__(256) void scores_kernel() {
    int nh = blockIdx.z;
    int n = nh >> 4, h = nh & 15;
    int i0 = blockIdx.y * 64;
    int j0 = blockIdx.x * 64;
    const float* qbase = g_qkv + (size_t)n * SEQ * (3 * DM) + h * HDIM;
    const float* kbase = g_qkv + (size_t)n * SEQ * (3 * DM) + DM + h * HDIM;

    __shared__ float Qs[64][64];  // [d][i]
    __shared__ float Ks[64][64];  // [d][j]

    int tid = threadIdx.x;
    int lr = tid >> 2;             // 0..63 (row)
    int lc = (tid & 3) * 16;       // col group base
    #pragma unroll
    for (int m4 = 0; m4 < 4; m4++) {
        float4 qv = *(const float4*)(qbase + (size_t)(i0 + lr) * (3 * DM) + lc + m4 * 4);
        float4 kv = *(const float4*)(kbase + (size_t)(j0 + lr) * (3 * DM) + lc + m4 * 4);
        Qs[lc + m4 * 4 + 0][lr] = qv.x; Qs[lc + m4 * 4 + 1][lr] = qv.y;
        Qs[lc + m4 * 4 + 2][lr] = qv.z; Qs[lc + m4 * 4 + 3][lr] = qv.w;
        Ks[lc + m4 * 4 + 0][lr] = kv.x; Ks[lc + m4 * 4 + 1][lr] = kv.y;
        Ks[lc + m4 * 4 + 2][lr] = kv.z; Ks[lc + m4 * 4 + 3][lr] = kv.w;
    }
    __syncthreads();

    int ty = tid >> 4, tx = tid & 15;
    int i_l = ty * 4, j_l = tx * 4;
    float acc[4][4];
    #pragma unroll
    for (int a = 0; a < 4; a++)
        #pragma unroll
        for (int b = 0; b < 4; b++) acc[a][b] = 0.f;

    #pragma unroll 8
    for (int d = 0; d < 64; d++) {
        float4 q4 = *(float4*)&Qs[d][i_l];
        float4 k4 = *(float4*)&Ks[d][j_l];
        float qa[4] = {q4.x, q4.y, q4.z, q4.w};
        float ka[4] = {k4.x, k4.y, k4.z, k4.w};
        #pragma unroll
        for (int a = 0; a < 4; a++)
            #pragma unroll
            for (int b = 0; b < 4; b++)
                acc[a][b] = fmaf(qa[a], ka[b], acc[a][b]);
    }
    float* sdst = g_scores + (size_t)nh * SEQ * SEQ;
    #pragma unroll
    for (int a = 0; a < 4; a++) {
        float4 v = make_float4(acc[a][0] * 0.125f, acc[a][1] * 0.125f,
                               acc[a][2] * 0.125f, acc[a][3] * 0.125f);
        *(float4*)(sdst + (size_t)(i0 + i_l + a) * SEQ + j0 + j_l) = v;
    }
}

// ---------------- softmax over rows of g_scores -------------------------------
__global__ void softmax_kernel() {
    __shared__ float sh[32];
    size_t row = blockIdx.x;
    float* p = g_scores + row * SEQ;
    int tid = threadIdx.x;  // 256
    float v[4];
    float m = -INFINITY;
    #pragma unroll
    for (int i = 0; i < 4; i++) { v[i] = p[tid + i * 256]; m = fmaxf(m, v[i]); }
    m = block_reduce_max(m, sh);
    float s = 0.f;
    #pragma unroll
    for (int i = 0; i < 4; i++) { v[i] = __expf(v[i] - m); s += v[i]; }
    s = block_reduce_sum(s, sh);
    float inv = 1.0f / s;
    #pragma unroll
    for (int i = 0; i < 4; i++) p[tid + i * 256] = v[i] * inv;
}

// ---------------- ctx = attn @ V ----------------------------------------------
__global__ __launch_bounds__(256) void ctx_kernel() {
    int nh = blockIdx.y;
    int n = nh >> 4, h = nh & 15;
    int i0 = blockIdx.x * 64;
    const float* attn  = g_scores + (size_t)nh * SEQ * SEQ;
    const float* vbase = g_qkv + (size_t)n * SEQ * (3 * DM) + 2 * DM + h * HDIM;
    float* cbase = g_ctx + (size_t)n * SEQ * DM + h * HDIM;

    __shared__ float As[64][64];  // [j][i] (transposed attn tile)
    __shared__ float Vs[64][64];  // [j][d]

    int tid = threadIdx.x;
    int lr = tid >> 2;
    int lc = (tid & 3) * 16;
    int ty = tid >> 4, tx = tid & 15;
    int i_l = ty * 4, d_l = tx * 4;

    float acc[4][4];
    #pragma unroll
    for (int a = 0; a < 4; a++)
        #pragma unroll
        for (int b = 0; b < 4; b++) acc[a][b] = 0.f;

    for (int j0 = 0; j0 < SEQ; j0 += 64) {
        #pragma unroll
        for (int m4 = 0; m4 < 4; m4++) {
            float4 av = *(const float4*)(attn + (size_t)(i0 + lr) * SEQ + j0 + lc + m4 * 4);
            As[lc + m4 * 4 + 0][lr] = av.x; As[lc + m4 * 4 + 1][lr] = av.y;
            As[lc + m4 * 4 + 2][lr] = av.z; As[lc + m4 * 4 + 3][lr] = av.w;
            float4 vv = *(const float4*)(vbase + (size_t)(j0 + lr) * (3 * DM) + lc + m4 * 4);
            *(float4*)&Vs[lr][lc + m4 * 4] = vv;
        }
        __syncthreads();
        #pragma unroll 8
        for (int j = 0; j < 64; j++) {
            float4 a4 = *(float4*)&As[j][i_l];
            float4 v4 = *(float4*)&Vs[j][d_l];
            float aa[4] = {a4.x, a4.y, a4.z, a4.w};
            float va[4] = {v4.x, v4.y, v4.z, v4.w};
            #pragma unroll
            for (int a = 0; a < 4; a++)
                #pragma unroll
                for (int b = 0; b < 4; b++)
                    acc[a][b] = fmaf(aa[a], va[b], acc[a][b]);
        }
        __syncthreads();
    }
    #pragma unroll
    for (int a = 0; a < 4; a++) {
        float4 v = make_float4(acc[a][0], acc[a][1], acc[a][2], acc[a][3]);
        *(float4*)(cbase + (size_t)(i0 + i_l + a) * DM + d_l) = v;
    }
}

// ---------------- residual + rmsnorm ------------------------------------------
__global__ void resid_rms_kernel(const float* __restrict__ hidden) {
    __shared__ float sh[32];
    int ns = blockIdx.x;              // 0..8191
    int n = ns >> 10, s = ns & 1023;
    const float* xr = hidden + ((size_t)(n >> 1) * SEQ + s) * DM;
    const float* ar = g_ao + ((size_t)n * SEQ + s) * DM;
    float* o = g_x1 + ((size_t)n * SEQ + s) * DM;
    int tid = threadIdx.x;            // 256
    float y[4];
    float ss = 0.f;
    #pragma unroll
    for (int i = 0; i < 4; i++) {
        int d = tid + i * 256;
        y[i] = xr[d] + ar[d];
        ss = fmaf(y[i], y[i], ss);
    }
    ss = block_reduce_sum(ss, sh);
    float scale = rsqrtf(ss * (1.0f / (float)DM) + EPS);
    #pragma unroll
    for (int i = 0; i < 4; i++) o[tid + i * 256] = y[i] * scale;
}

// ---------------- silu(gate) * up ----------------------------------------------
__global__ void act_kernel() {
    size_t idx = (size_t)blockIdx.x * blockDim.x + threadIdx.x;
    size_t r = idx / INTER;
    int i = (int)(idx % INTER);
    float g = g_gu[r * (2 * INTER) + i];
    float u = g_gu[r * (2 * INTER) + INTER + i];
    float sg = g / (1.0f + __expf(-g));
    g_act[idx] = sg * u;
}

// ---------------- final: rmsnorm(x1 + mlp), weighted top-2 combine -------------
__global__ void final_kernel(float* __restrict__ out) {
    __shared__ float sh[32];
    int bs = blockIdx.x;              // 4096: b,s
    int b = bs >> 10, s = bs & 1023;
    int tid = threadIdx.x;            // 256
    int n0 = 2 * b, n1 = 2 * b + 1;
    size_t base0 = ((size_t)n0 * SEQ + s) * DM;
    size_t base1 = ((size_t)n1 * SEQ + s) * DM;
    float y0[4], y1[4];
    float ss0 = 0.f, ss1 = 0.f;
    #pragma unroll
    for (int i = 0; i < 4; i++) {
        int d = tid + i * 256;
        y0[i] = g_x1[base0 + d] + g_mlp[base0 + d];
        y1[i] = g_x1[base1 + d] + g_mlp[base1 + d];
        ss0 = fmaf(y0[i], y0[i], ss0);
        ss1 = fmaf(y1[i], y1[i], ss1);
    }
    ss0 = block_reduce_sum(ss0, sh);
    ss1 = block_reduce_sum(ss1, sh);
    float r0 = rsqrtf(ss0 * (1.0f / (float)DM) + EPS) * g_w[n0];
    float r1 = rsqrtf(ss1 * (1.0f / (float)DM) + EPS) * g_w[n1];
    float* orow = out + ((size_t)b * SEQ + s) * DM;
    #pragma unroll
    for (int i = 0; i < 4; i++) {
        int d = tid + i * 256;
        orow[d] = y0[i] * r0 + y1[i] * r1;
    }
}

// ---------------- host launcher --------------------------------------------------
extern "C" void kernel_launch(void* const* d_in, const int* in_sizes, int n_in,
                              void* d_out, int out_size) {
    const float* hidden = (const float*)d_in[0];
    const float* cosb   = (const float*)d_in[1];
    const float* sinb   = (const float*)d_in[2];
    const float* Wr     = (const float*)d_in[3];
    const float* temp   = (const float*)d_in[4];
    const float* Wqkv   = (const float*)d_in[5];
    const float* Wo     = (const float*)d_in[6];
    const float* Wgu    = (const float*)d_in[7];
    const float* Wd     = (const float*)d_in[8];
    float* out = (float*)d_out;

    float *p_qkv, *p_ctx, *p_ao, *p_x1, *p_gu, *p_act, *p_mlp;
    cudaGetSymbolAddress((void**)&p_qkv, g_qkv);
    cudaGetSymbolAddress((void**)&p_ctx, g_ctx);
    cudaGetSymbolAddress((void**)&p_ao,  g_ao);
    cudaGetSymbolAddress((void**)&p_x1,  g_x1);
    cudaGetSymbolAddress((void**)&p_gu,  g_gu);
    cudaGetSymbolAddress((void**)&p_act, g_act);
    cudaGetSymbolAddress((void**)&p_mlp, g_mlp);

    // routing
    mean1_kernel<<<dim3(BATCH, 16), 256>>>(hidden);
    mean2_kernel<<<BATCH, 256>>>();
    routing_kernel<<<1, 1024>>>(Wr, temp, out + (size_t)BATCH * SEQ * DM);

    // qkv = x @ Wqkv[e]
    sgemm_kernel<<<dim3(3 * DM / BN, SEQ / BM, NSAMP), 256>>>(
        hidden, Wqkv, p_qkv, SEQ, 3 * DM, DM, 1);

    // rope in-place
    rope_kernel<<<dim3(SEQ, NSAMP), 512>>>(cosb, sinb);

    // attention
    scores_kernel<<<dim3(SEQ / 64, SEQ / 64, NSAMP * HN), 256>>>();
    softmax_kernel<<<NSAMP * HN * SEQ, 256>>>();
    ctx_kernel<<<dim3(SEQ / 64, NSAMP * HN), 256>>>();

    // attn_out = ctx @ Wo[e]
    sgemm_kernel<<<dim3(DM / BN, SEQ / BM, NSAMP), 256>>>(
        p_ctx, Wo, p_ao, SEQ, DM, DM, 0);

    // x1 = rmsnorm(x + attn_out)
    resid_rms_kernel<<<NSAMP * SEQ, 256>>>(hidden);

    // gu = x1 @ Wgu[e]
    sgemm_kernel<<<dim3(2 * INTER / BN, SEQ / BM, NSAMP), 256>>>(
        p_x1, Wgu, p_gu, SEQ, 2 * INTER, DM, 0);

    // act = silu(gate) * up
    act_kernel<<<(NSAMP * SEQ * INTER) / 256, 256>>>();

    // mlp = act @ Wd[e]
    sgemm_kernel<<<dim3(DM / BN, SEQ / BM, NSAMP), 256>>>(
        p_act, Wd, p_mlp, SEQ, DM, INTER, 0);

    // out = sum of weighted rmsnorm(x1 + mlp)
    final_kernel<<<BATCH * SEQ, 256>>>(out);
}

// round 2
// speedup vs baseline: 2.6263x; 2.6263x over previous
#include <cuda_runtime.h>
#include <math.h>
#include <stdint.h>

#define SEQ   1024
#define DM    1024
#define HN    16
#define HDIM  64
#define NSAMP 8
#define INTER 768
#define BATCH 4
#define EPS   1e-5f

// ---------------- scratch (device globals; no allocations allowed) ----------
__device__ float g_hsmean[BATCH * DM];
__device__ float g_partial[BATCH * 16 * DM];
__device__ int   g_expert[NSAMP];
__device__ float g_w[NSAMP];
__device__ float g_qkv[(size_t)NSAMP * SEQ * 3 * DM];        // 96 MB
__device__ float g_scores[(size_t)NSAMP * HN * SEQ * SEQ];   // 512 MB
__device__ float g_ctx[(size_t)NSAMP * SEQ * DM];            // 32 MB
__device__ float g_ao[(size_t)NSAMP * SEQ * DM];             // 32 MB
__device__ float g_x1[(size_t)NSAMP * SEQ * DM];             // 32 MB
__device__ float g_gu[(size_t)NSAMP * SEQ * 2 * INTER];      // 48 MB
__device__ float g_act[(size_t)NSAMP * SEQ * INTER];         // 24 MB
__device__ float g_mlp[(size_t)NSAMP * SEQ * DM];            // 32 MB

// ---------------- small helpers ----------------------------------------------
__device__ __forceinline__ float block_reduce_sum(float v, float* sh) {
    int tid = threadIdx.x;
    #pragma unroll
    for (int o = 16; o; o >>= 1) v += __shfl_down_sync(0xFFFFFFFFu, v, o);
    if ((tid & 31) == 0) sh[tid >> 5] = v;
    __syncthreads();
    float r = 0.f;
    if (tid < 32) {
        float x = (tid < (int)(blockDim.x >> 5)) ? sh[tid] : 0.f;
        #pragma unroll
        for (int o = 16; o; o >>= 1) x += __shfl_down_sync(0xFFFFFFFFu, x, o);
        if (tid == 0) sh[0] = x;
    }
    __syncthreads();
    r = sh[0];
    __syncthreads();
    return r;
}

__device__ __forceinline__ float block_reduce_max(float v, float* sh) {
    int tid = threadIdx.x;
    #pragma unroll
    for (int o = 16; o; o >>= 1) v = fmaxf(v, __shfl_down_sync(0xFFFFFFFFu, v, o));
    if ((tid & 31) == 0) sh[tid >> 5] = v;
    __syncthreads();
    float r;
    if (tid < 32) {
        float x = (tid < (int)(blockDim.x >> 5)) ? sh[tid] : -INFINITY;
        #pragma unroll
        for (int o = 16; o; o >>= 1) x = fmaxf(x, __shfl_down_sync(0xFFFFFFFFu, x, o));
        if (tid == 0) sh[0] = x;
    }
    __syncthreads();
    r = sh[0];
    __syncthreads();
    return r;
}

__device__ __forceinline__ uint32_t f2tf32(float x) {
    uint32_t r;
    asm("cvt.rna.tf32.f32 %0, %1;" : "=r"(r) : "f"(x));
    return r;
}

__device__ __forceinline__ void mma_tf32(float* d, const uint32_t* a, const uint32_t* b) {
    asm volatile(
        "mma.sync.aligned.m16n8k8.row.col.f32.tf32.tf32.f32 "
        "{%0,%1,%2,%3},{%4,%5,%6,%7},{%8,%9},{%0,%1,%2,%3};"
        : "+f"(d[0]), "+f"(d[1]), "+f"(d[2]), "+f"(d[3])
        : "r"(a[0]), "r"(a[1]), "r"(a[2]), "r"(a[3]), "r"(b[0]), "r"(b[1]));
}

__device__ __forceinline__ void cp16(uint32_t s, const void* g) {
    asm volatile("cp.async.cg.shared.global [%0], [%1], 16;" :: "r"(s), "l"(g));
}
__device__ __forceinline__ void cp_commit() {
    asm volatile("cp.async.commit_group;" ::: "memory");
}
__device__ __forceinline__ void cp_wait0() {
    asm volatile("cp.async.wait_group 0;" ::: "memory");
}

// ---------------- routing ----------------------------------------------------
__global__ void mean1_kernel(const float* __restrict__ hidden) {
    int b = blockIdx.x, c = blockIdx.y;
    int tid = threadIdx.x;
    float acc[4] = {0.f, 0.f, 0.f, 0.f};
    for (int s = c * 64; s < c * 64 + 64; s++) {
        const float* row = hidden + ((size_t)b * SEQ + s) * DM;
        #pragma unroll
        for (int i = 0; i < 4; i++) acc[i] += row[tid + i * 256];
    }
    #pragma unroll
    for (int i = 0; i < 4; i++)
        g_partial[((size_t)b * 16 + c) * DM + tid + i * 256] = acc[i];
}

__global__ void mean2_kernel() {
    int b = blockIdx.x;
    int tid = threadIdx.x;
    #pragma unroll
    for (int i = 0; i < 4; i++) {
        int d = tid + i * 256;
        float s = 0.f;
        for (int c = 0; c < 16; c++) s += g_partial[((size_t)b * 16 + c) * DM + d];
        g_hsmean[b * DM + d] = s * (1.0f / (float)SEQ);
    }
}

__global__ void routing_kernel(const float* __restrict__ Wr,
                               const float* __restrict__ temperature,
                               float* __restrict__ out_logits) {
    int tid = threadIdx.x;          // 1024
    int w = tid >> 5, lane = tid & 31;
    int b = w >> 3, c = w & 7;
    float s = 0.f;
    for (int d = lane; d < DM; d += 32)
        s += g_hsmean[b * DM + d] * Wr[c * DM + d];
    #pragma unroll
    for (int o = 16; o; o >>= 1) s += __shfl_down_sync(0xFFFFFFFFu, s, o);
    __shared__ float logits[32];
    if (lane == 0) logits[w] = s;
    __syncthreads();
    if (tid < BATCH) {
        float t = fminf(fmaxf(temperature[0], 0.1f), 10.0f);
        float lv[8];
        #pragma unroll
        for (int cc = 0; cc < 8; cc++) {
            lv[cc] = logits[tid * 8 + cc] / t;
            out_logits[tid * 8 + cc] = lv[cc];
        }
        int i0 = 0;
        #pragma unroll
        for (int cc = 1; cc < 8; cc++) if (lv[cc] > lv[i0]) i0 = cc;
        int i1 = -1;
        #pragma unroll
        for (int cc = 0; cc < 8; cc++) {
            if (cc == i0) continue;
            if (i1 < 0 || lv[cc] > lv[i1]) i1 = cc;
        }
        float e = expf(lv[i1] - lv[i0]);
        g_expert[2 * tid]     = i0;
        g_expert[2 * tid + 1] = i1;
        g_w[2 * tid]     = 1.0f / (1.0f + e);
        g_w[2 * tid + 1] = e / (1.0f + e);
    }
}

// ---------------- generic tf32 tensor-core GEMM -------------------------------
// C[z] = alpha * A[z] @ B[z],  A: MxK (lda), B: KxN (ldb) or transposed view,
// per-z bases: z1 = z / Z0, z0 = z % Z0.
template<int BM, int BN, int WPM, int WPN, bool TB>
__global__ __launch_bounds__(256) void mma_gemm(
    const float* __restrict__ Ab, const float* __restrict__ Bb, float* __restrict__ Cb,
    int M, int N, int K, int lda, int ldb, int ldc,
    int Z0, long long sa1, long long sa0, long long sb1, long long sb0,
    long long sc1, long long sc0, int useExpert, long long sbExp, float alpha)
{
    constexpr int BK   = 16;
    constexpr int ASTR = BK + 4;                 // 20: (20r+c)%32 distinct
    constexpr int BSTR = TB ? (BK + 4) : (BN + 8);
    constexpr int BROWS = TB ? BN : BK;
    constexpr int WM = BM / WPM, WN = BN / WPN;
    constexpr int MI = WM / 16, NJ = WN / 8;
    constexpr int ACH = BM * 4 / 256;            // float4 chunks per thread (A)
    constexpr int BCH = BN * 4 / 256;            // float4 chunks per thread (B)

    __shared__ float sA[2][BM * ASTR];
    __shared__ float sB[2][BROWS * BSTR];

    int z = blockIdx.z;
    int z1 = z / Z0, z0 = z % Z0;
    const float* A = Ab + z1 * sa1 + z0 * sa0;
    const float* B = useExpert ? (Bb + (long long)g_expert[z] * sbExp)
                               : (Bb + z1 * sb1 + z0 * sb0);
    float* C = Cb + z1 * sc1 + z0 * sc0;

    int row0 = blockIdx.y * BM;
    int n0   = blockIdx.x * BN;
    int tid = threadIdx.x, lane = tid & 31, wid = tid >> 5;
    int wm0 = (wid % WPM) * WM;
    int wn0 = (wid / WPM) * WN;
    int g = lane >> 2, t = lane & 3;

    uint32_t sAu = (uint32_t)__cvta_generic_to_shared(&sA[0][0]);
    uint32_t sBu = (uint32_t)__cvta_generic_to_shared(&sB[0][0]);

    float acc[MI][NJ][4];
    #pragma unroll
    for (int i = 0; i < MI; i++)
        #pragma unroll
        for (int j = 0; j < NJ; j++)
            #pragma unroll
            for (int q = 0; q < 4; q++) acc[i][j][q] = 0.f;

    auto load_tiles = [&](int k0, int buf) {
        #pragma unroll
        for (int p = 0; p < ACH; p++) {
            int i = tid + p * 256;
            int m = i >> 2, kc = (i & 3) * 4;
            cp16(sAu + (uint32_t)(buf * BM * ASTR + m * ASTR + kc) * 4,
                 A + (size_t)(row0 + m) * lda + k0 + kc);
        }
        if (TB) {
            #pragma unroll
            for (int p = 0; p < BCH; p++) {
                int i = tid + p * 256;
                int n = i >> 2, kc = (i & 3) * 4;
                cp16(sBu + (uint32_t)(buf * BROWS * BSTR + n * BSTR + kc) * 4,
                     B + (size_t)(n0 + n) * ldb + k0 + kc);
            }
        } else {
            #pragma unroll
            for (int p = 0; p < BCH; p++) {
                int i = tid + p * 256;
                int k = i / (BN / 4), nc = (i % (BN / 4)) * 4;
                cp16(sBu + (uint32_t)(buf * BROWS * BSTR + k * BSTR + nc) * 4,
                     B + (size_t)(k0 + k) * ldb + n0 + nc);
            }
        }
    };

    int NT = K / BK;
    load_tiles(0, 0);
    cp_commit();

    for (int tI = 0; tI < NT; ++tI) {
        cp_wait0();
        __syncthreads();
        if (tI + 1 < NT) {
            load_tiles((tI + 1) * BK, (tI + 1) & 1);
            cp_commit();
        }
        const float* a = sA[tI & 1];
        const float* b = sB[tI & 1];
        #pragma unroll
        for (int ks = 0; ks < 2; ks++) {
            int kk = ks * 8;
            uint32_t af[MI][4];
            uint32_t bf[NJ][2];
            #pragma unroll
            for (int i = 0; i < MI; i++) {
                int r = wm0 + i * 16 + g;
                af[i][0] = f2tf32(a[r * ASTR + kk + t]);
                af[i][1] = f2tf32(a[(r + 8) * ASTR + kk + t]);
                af[i][2] = f2tf32(a[r * ASTR + kk + t + 4]);
                af[i][3] = f2tf32(a[(r + 8) * ASTR + kk + t + 4]);
            }
            #pragma unroll
            for (int j = 0; j < NJ; j++) {
                int n = wn0 + j * 8 + g;
                if (TB) {
                    bf[j][0] = f2tf32(b[n * BSTR + kk + t]);
                    bf[j][1] = f2tf32(b[n * BSTR + kk + t + 4]);
                } else {
                    bf[j][0] = f2tf32(b[(kk + t) * BSTR + n]);
                    bf[j][1] = f2tf32(b[(kk + t + 4) * BSTR + n]);
                }
            }
            #pragma unroll
            for (int i = 0; i < MI; i++)
                #pragma unroll
                for (int j = 0; j < NJ; j++)
                    mma_tf32(acc[i][j], af[i], bf[j]);
        }
        __syncthreads();
    }

    #pragma unroll
    for (int i = 0; i < MI; i++) {
        #pragma unroll
        for (int j = 0; j < NJ; j++) {
            int r = row0 + wm0 + i * 16 + g;
            int c = n0 + wn0 + j * 8 + t * 2;
            float2 v0 = make_float2(acc[i][j][0] * alpha, acc[i][j][1] * alpha);
            float2 v1 = make_float2(acc[i][j][2] * alpha, acc[i][j][3] * alpha);
            *(float2*)(C + (size_t)r * ldc + c) = v0;
            *(float2*)(C + (size_t)(r + 8) * ldc + c) = v1;
        }
    }
}

// ---------------- RoPE (in-place on q,k inside g_qkv) ------------------------
__global__ void rope_kernel(const float* __restrict__ cosb, const float* __restrict__ sinb) {
    int s = blockIdx.x, n = blockIdx.y;
    int tid = threadIdx.x;            // 512
    int h = tid >> 5, j = tid & 31;
    float c0 = cosb[s * HDIM + j],      s0 = sinb[s * HDIM + j];
    float c1 = cosb[s * HDIM + j + 32], s1 = sinb[s * HDIM + j + 32];
    float* row = g_qkv + ((size_t)n * SEQ + s) * (3 * DM);
    float* q = row + h * HDIM;
    float qa = q[j], qb = q[j + 32];
    q[j]      = qa * c0 - qb * s0;
    q[j + 32] = qb * c1 + qa * s1;
    float* k = row + DM + h * HDIM;
    float ka = k[j], kb = k[j + 32];
    k[j]      = ka * c0 - kb * s0;
    k[j + 32] = kb * c1 + ka * s1;
}

// ---------------- softmax over rows of g_scores -------------------------------
__global__ void softmax_kernel() {
    __shared__ float sh[32];
    size_t row = blockIdx.x;
    float* p = g_scores + row * SEQ;
    int tid = threadIdx.x;  // 256
    float v[4];
    float m = -INFINITY;
    #pragma unroll
    for (int i = 0; i < 4; i++) { v[i] = p[tid + i * 256]; m = fmaxf(m, v[i]); }
    m = block_reduce_max(m, sh);
    float s = 0.f;
    #pragma unroll
    for (int i = 0; i < 4; i++) { v[i] = __expf(v[i] - m); s += v[i]; }
    s = block_reduce_sum(s, sh);
    float inv = 1.0f / s;
    #pragma unroll
    for (int i = 0; i < 4; i++) p[tid + i * 256] = v[i] * inv;
}

// ---------------- residual + rmsnorm ------------------------------------------
__global__ void resid_rms_kernel(const float* __restrict__ hidden) {
    __shared__ float sh[32];
    int ns = blockIdx.x;
    int n = ns >> 10, s = ns & 1023;
    const float* xr = hidden + ((size_t)(n >> 1) * SEQ + s) * DM;
    const float* ar = g_ao + ((size_t)n * SEQ + s) * DM;
    float* o = g_x1 + ((size_t)n * SEQ + s) * DM;
    int tid = threadIdx.x;
    float y[4];
    float ss = 0.f;
    #pragma unroll
    for (int i = 0; i < 4; i++) {
        int d = tid + i * 256;
        y[i] = xr[d] + ar[d];
        ss = fmaf(y[i], y[i], ss);
    }
    ss = block_reduce_sum(ss, sh);
    float scale = rsqrtf(ss * (1.0f / (float)DM) + EPS);
    #pragma unroll
    for (int i = 0; i < 4; i++) o[tid + i * 256] = y[i] * scale;
}

// ---------------- silu(gate) * up ----------------------------------------------
__global__ void act_kernel() {
    size_t idx = (size_t)blockIdx.x * blockDim.x + threadIdx.x;
    size_t r = idx / INTER;
    int i = (int)(idx % INTER);
    float g = g_gu[r * (2 * INTER) + i];
    float u = g_gu[r * (2 * INTER) + INTER + i];
    float sg = g / (1.0f + __expf(-g));
    g_act[idx] = sg * u;
}

// ---------------- final: rmsnorm(x1 + mlp), weighted top-2 combine -------------
__global__ void final_kernel(float* __restrict__ out) {
    __shared__ float sh[32];
    int bs = blockIdx.x;
    int b = bs >> 10, s = bs & 1023;
    int tid = threadIdx.x;
    int n0 = 2 * b, n1 = 2 * b + 1;
    size_t base0 = ((size_t)n0 * SEQ + s) * DM;
    size_t base1 = ((size_t)n1 * SEQ + s) * DM;
    float y0[4], y1[4];
    float ss0 = 0.f, ss1 = 0.f;
    #pragma unroll
    for (int i = 0; i < 4; i++) {
        int d = tid + i * 256;
        y0[i] = g_x1[base0 + d] + g_mlp[base0 + d];
        y1[i] = g_x1[base1 + d] + g_mlp[base1 + d];
        ss0 = fmaf(y0[i], y0[i], ss0);
        ss1 = fmaf(y1[i], y1[i], ss1);
    }
    ss0 = block_reduce_sum(ss0, sh);
    ss1 = block_reduce_sum(ss1, sh);
    float r0 = rsqrtf(ss0 * (1.0f / (float)DM) + EPS) * g_w[n0];
    float r1 = rsqrtf(ss1 * (1.0f / (float)DM) + EPS) * g_w[n1];
    float* orow = out + ((size_t)b * SEQ + s) * DM;
    #pragma unroll
    for (int i = 0; i < 4; i++) {
        int d = tid + i * 256;
        orow[d] = y0[i] * r0 + y1[i] * r1;
    }
}

// ---------------- host launcher --------------------------------------------------
extern "C" void kernel_launch(void* const* d_in, const int* in_sizes, int n_in,
                              void* d_out, int out_size) {
    const float* hidden = (const float*)d_in[0];
    const float* cosb   = (const float*)d_in[1];
    const float* sinb   = (const float*)d_in[2];
    const float* Wr     = (const float*)d_in[3];
    const float* temp   = (const float*)d_in[4];
    const float* Wqkv   = (const float*)d_in[5];
    const float* Wo     = (const float*)d_in[6];
    const float* Wgu    = (const float*)d_in[7];
    const float* Wd     = (const float*)d_in[8];
    float* out = (float*)d_out;

    float *p_qkv, *p_scores, *p_ctx, *p_ao, *p_x1, *p_gu, *p_act, *p_mlp;
    cudaGetSymbolAddress((void**)&p_qkv,    g_qkv);
    cudaGetSymbolAddress((void**)&p_scores, g_scores);
    cudaGetSymbolAddress((void**)&p_ctx,    g_ctx);
    cudaGetSymbolAddress((void**)&p_ao,     g_ao);
    cudaGetSymbolAddress((void**)&p_x1,     g_x1);
    cudaGetSymbolAddress((void**)&p_gu,     g_gu);
    cudaGetSymbolAddress((void**)&p_act,    g_act);
    cudaGetSymbolAddress((void**)&p_mlp,    g_mlp);

    // routing
    mean1_kernel<<<dim3(BATCH, 16), 256>>>(hidden);
    mean2_kernel<<<BATCH, 256>>>();
    routing_kernel<<<1, 1024>>>(Wr, temp, out + (size_t)BATCH * SEQ * DM);

    // qkv = x @ Wqkv[e]   (M=1024, N=3072, K=1024)
    mma_gemm<128, 128, 2, 4, false><<<dim3(3072 / 128, SEQ / 128, NSAMP), 256>>>(
        hidden, Wqkv, p_qkv, SEQ, 3 * DM, DM, DM, 3 * DM, 3 * DM,
        2, (long long)SEQ * DM, 0, 0, 0,
        2LL * SEQ * 3 * DM, (long long)SEQ * 3 * DM,
        1, (long long)DM * 3 * DM, 1.0f);

    // rope in-place
    rope_kernel<<<dim3(SEQ, NSAMP), 512>>>(cosb, sinb);

    // scores = Q @ K^T / 8   (per (n,h): M=N=1024, K=64, TB)
    mma_gemm<128, 128, 2, 4, true><<<dim3(SEQ / 128, SEQ / 128, NSAMP * HN), 256>>>(
        p_qkv, p_qkv + DM, p_scores, SEQ, SEQ, HDIM, 3 * DM, 3 * DM, SEQ,
        HN, (long long)SEQ * 3 * DM, HDIM,
        (long long)SEQ * 3 * DM, HDIM,
        (long long)HN * SEQ * SEQ, (long long)SEQ * SEQ,
        0, 0, 0.125f);

    softmax_kernel<<<NSAMP * HN * SEQ, 256>>>();

    // ctx = attn @ V   (per (n,h): M=1024, N=64, K=1024)
    mma_gemm<128, 64, 4, 2, false><<<dim3(1, SEQ / 128, NSAMP * HN), 256>>>(
        p_scores, p_qkv + 2 * DM, p_ctx, SEQ, HDIM, SEQ, SEQ, 3 * DM, DM,
        HN, (long long)HN * SEQ * SEQ, (long long)SEQ * SEQ,
        (long long)SEQ * 3 * DM, HDIM,
        (long long)SEQ * DM, HDIM,
        0, 0, 1.0f);

    // attn_out = ctx @ Wo[e]   (1024 x 1024 x 1024)
    mma_gemm<128, 128, 2, 4, false><<<dim3(DM / 128, SEQ / 128, NSAMP), 256>>>(
        p_ctx, Wo, p_ao, SEQ, DM, DM, DM, DM, DM,
        1, (long long)SEQ * DM, 0, 0, 0,
        (long long)SEQ * DM, 0,
        1, (long long)DM * DM, 1.0f);

    // x1 = rmsnorm(x + attn_out)
    resid_rms_kernel<<<NSAMP * SEQ, 256>>>(hidden);

    // gu = x1 @ Wgu[e]   (1024 x 1536 x 1024)
    mma_gemm<128, 128, 2, 4, false><<<dim3(2 * INTER / 128, SEQ / 128, NSAMP), 256>>>(
        p_x1, Wgu, p_gu, SEQ, 2 * INTER, DM, DM, 2 * INTER, 2 * INTER,
        1, (long long)SEQ * DM, 0, 0, 0,
        (long long)SEQ * 2 * INTER, 0,
        1, (long long)DM * 2 * INTER, 1.0f);

    // act = silu(gate) * up
    act_kernel<<<(NSAMP * SEQ * INTER) / 256, 256>>>();

    // mlp = act @ Wd[e]   (1024 x 1024 x 768)
    mma_gemm<128, 128, 2, 4, false><<<dim3(DM / 128, SEQ / 128, NSAMP), 256>>>(
        p_act, Wd, p_mlp, SEQ, DM, INTER, INTER, DM, DM,
        1, (long long)SEQ * INTER, 0, 0, 0,
        (long long)SEQ * DM, 0,
        1, (long long)INTER * DM, 1.0f);

    // out = sum of weighted rmsnorm(x1 + mlp)
    final_kernel<<<BATCH * SEQ, 256>>>(out);
}

// round 3
// speedup vs baseline: 3.6379x; 1.3852x over previous
#include <cuda_runtime.h>
#include <math.h>
#include <stdint.h>

#define SEQ   1024
#define DM    1024
#define HN    16
#define HDIM  64
#define NSAMP 8
#define INTER 768
#define BATCH 4
#define EPS   1e-5f

// ---------------- scratch (device globals; no allocations allowed) ----------
__device__ float g_hsmean[BATCH * DM];
__device__ float g_partial[BATCH * 16 * DM];
__device__ int   g_expert[NSAMP];
__device__ float g_w[NSAMP];
__device__ float g_qkv[(size_t)NSAMP * SEQ * 3 * DM];        // 96 MB
__device__ float g_ctx[(size_t)NSAMP * SEQ * DM];            // 32 MB
__device__ float g_ao[(size_t)NSAMP * SEQ * DM];             // 32 MB
__device__ float g_x1[(size_t)NSAMP * SEQ * DM];             // 32 MB
__device__ float g_gu[(size_t)NSAMP * SEQ * 2 * INTER];      // 48 MB
__device__ float g_act[(size_t)NSAMP * SEQ * INTER];         // 24 MB
__device__ float g_mlp[(size_t)NSAMP * SEQ * DM];            // 32 MB

// ---------------- small helpers ----------------------------------------------
__device__ __forceinline__ float block_reduce_sum(float v, float* sh) {
    int tid = threadIdx.x;
    #pragma unroll
    for (int o = 16; o; o >>= 1) v += __shfl_down_sync(0xFFFFFFFFu, v, o);
    if ((tid & 31) == 0) sh[tid >> 5] = v;
    __syncthreads();
    float r = 0.f;
    if (tid < 32) {
        float x = (tid < (int)(blockDim.x >> 5)) ? sh[tid] : 0.f;
        #pragma unroll
        for (int o = 16; o; o >>= 1) x += __shfl_down_sync(0xFFFFFFFFu, x, o);
        if (tid == 0) sh[0] = x;
    }
    __syncthreads();
    r = sh[0];
    __syncthreads();
    return r;
}

__device__ __forceinline__ void mma_tf32(float* d, const uint32_t* a, const uint32_t* b) {
    asm volatile(
        "mma.sync.aligned.m16n8k8.row.col.f32.tf32.tf32.f32 "
        "{%0,%1,%2,%3},{%4,%5,%6,%7},{%8,%9},{%0,%1,%2,%3};"
        : "+f"(d[0]), "+f"(d[1]), "+f"(d[2]), "+f"(d[3])
        : "r"(a[0]), "r"(a[1]), "r"(a[2]), "r"(a[3]), "r"(b[0]), "r"(b[1]));
}

__device__ __forceinline__ void cp16(uint32_t s, const void* g) {
    asm volatile("cp.async.cg.shared.global [%0], [%1], 16;" :: "r"(s), "l"(g));
}
__device__ __forceinline__ void cp_commit() {
    asm volatile("cp.async.commit_group;" ::: "memory");
}
__device__ __forceinline__ void cp_wait0() {
    asm volatile("cp.async.wait_group 0;" ::: "memory");
}

// ---------------- routing ----------------------------------------------------
__global__ void mean1_kernel(const float* __restrict__ hidden) {
    int b = blockIdx.x, c = blockIdx.y;
    int tid = threadIdx.x;
    float acc[4] = {0.f, 0.f, 0.f, 0.f};
    for (int s = c * 64; s < c * 64 + 64; s++) {
        const float* row = hidden + ((size_t)b * SEQ + s) * DM;
        #pragma unroll
        for (int i = 0; i < 4; i++) acc[i] += row[tid + i * 256];
    }
    #pragma unroll
    for (int i = 0; i < 4; i++)
        g_partial[((size_t)b * 16 + c) * DM + tid + i * 256] = acc[i];
}

__global__ void mean2_kernel() {
    int b = blockIdx.x;
    int tid = threadIdx.x;
    #pragma unroll
    for (int i = 0; i < 4; i++) {
        int d = tid + i * 256;
        float s = 0.f;
        for (int c = 0; c < 16; c++) s += g_partial[((size_t)b * 16 + c) * DM + d];
        g_hsmean[b * DM + d] = s * (1.0f / (float)SEQ);
    }
}

__global__ void routing_kernel(const float* __restrict__ Wr,
                               const float* __restrict__ temperature,
                               float* __restrict__ out_logits) {
    int tid = threadIdx.x;          // 1024
    int w = tid >> 5, lane = tid & 31;
    int b = w >> 3, c = w & 7;
    float s = 0.f;
    for (int d = lane; d < DM; d += 32)
        s += g_hsmean[b * DM + d] * Wr[c * DM + d];
    #pragma unroll
    for (int o = 16; o; o >>= 1) s += __shfl_down_sync(0xFFFFFFFFu, s, o);
    __shared__ float logits[32];
    if (lane == 0) logits[w] = s;
    __syncthreads();
    if (tid < BATCH) {
        float t = fminf(fmaxf(temperature[0], 0.1f), 10.0f);
        float lv[8];
        #pragma unroll
        for (int cc = 0; cc < 8; cc++) {
            lv[cc] = logits[tid * 8 + cc] / t;
            out_logits[tid * 8 + cc] = lv[cc];
        }
        int i0 = 0;
        #pragma unroll
        for (int cc = 1; cc < 8; cc++) if (lv[cc] > lv[i0]) i0 = cc;
        int i1 = -1;
        #pragma unroll
        for (int cc = 0; cc < 8; cc++) {
            if (cc == i0) continue;
            if (i1 < 0 || lv[cc] > lv[i1]) i1 = cc;
        }
        float e = expf(lv[i1] - lv[i0]);
        g_expert[2 * tid]     = i0;
        g_expert[2 * tid + 1] = i1;
        g_w[2 * tid]     = 1.0f / (1.0f + e);
        g_w[2 * tid + 1] = e / (1.0f + e);
    }
}

// ---------------- generic tf32 tensor-core GEMM -------------------------------
template<int BM, int BN, int WPM, int WPN, bool TB>
__global__ __launch_bounds__(256) void mma_gemm(
    const float* __restrict__ Ab, const float* __restrict__ Bb, float* __restrict__ Cb,
    int M, int N, int K, int lda, int ldb, int ldc,
    int Z0, long long sa1, long long sa0, long long sb1, long long sb0,
    long long sc1, long long sc0, int useExpert, long long sbExp, float alpha)
{
    constexpr int BK   = 16;
    constexpr int ASTR = BK + 4;
    constexpr int BSTR = TB ? (BK + 4) : (BN + 8);
    constexpr int BROWS = TB ? BN : BK;
    constexpr int WM = BM / WPM, WN = BN / WPN;
    constexpr int MI = WM / 16, NJ = WN / 8;
    constexpr int ACH = BM * 4 / 256;
    constexpr int BCH = BN * 4 / 256;

    __shared__ float sA[2][BM * ASTR];
    __shared__ float sB[2][BROWS * BSTR];

    int z = blockIdx.z;
    int z1 = z / Z0, z0 = z % Z0;
    const float* A = Ab + z1 * sa1 + z0 * sa0;
    const float* B = useExpert ? (Bb + (long long)g_expert[z] * sbExp)
                               : (Bb + z1 * sb1 + z0 * sb0);
    float* C = Cb + z1 * sc1 + z0 * sc0;

    int row0 = blockIdx.y * BM;
    int n0   = blockIdx.x * BN;
    int tid = threadIdx.x, lane = tid & 31, wid = tid >> 5;
    int wm0 = (wid % WPM) * WM;
    int wn0 = (wid / WPM) * WN;
    int g = lane >> 2, t = lane & 3;

    uint32_t sAu = (uint32_t)__cvta_generic_to_shared(&sA[0][0]);
    uint32_t sBu = (uint32_t)__cvta_generic_to_shared(&sB[0][0]);

    float acc[MI][NJ][4];
    #pragma unroll
    for (int i = 0; i < MI; i++)
        #pragma unroll
        for (int j = 0; j < NJ; j++)
            #pragma unroll
            for (int q = 0; q < 4; q++) acc[i][j][q] = 0.f;

    auto load_tiles = [&](int k0, int buf) {
        #pragma unroll
        for (int p = 0; p < ACH; p++) {
            int i = tid + p * 256;
            int m = i >> 2, kc = (i & 3) * 4;
            cp16(sAu + (uint32_t)(buf * BM * ASTR + m * ASTR + kc) * 4,
                 A + (size_t)(row0 + m) * lda + k0 + kc);
        }
        if (TB) {
            #pragma unroll
            for (int p = 0; p < BCH; p++) {
                int i = tid + p * 256;
                int n = i >> 2, kc = (i & 3) * 4;
                cp16(sBu + (uint32_t)(buf * BROWS * BSTR + n * BSTR + kc) * 4,
                     B + (size_t)(n0 + n) * ldb + k0 + kc);
            }
        } else {
            #pragma unroll
            for (int p = 0; p < BCH; p++) {
                int i = tid + p * 256;
                int k = i / (BN / 4), nc = (i % (BN / 4)) * 4;
                cp16(sBu + (uint32_t)(buf * BROWS * BSTR + k * BSTR + nc) * 4,
                     B + (size_t)(k0 + k) * ldb + n0 + nc);
            }
        }
    };

    int NT = K / BK;
    load_tiles(0, 0);
    cp_commit();

    for (int tI = 0; tI < NT; ++tI) {
        cp_wait0();
        __syncthreads();
        if (tI + 1 < NT) {
            load_tiles((tI + 1) * BK, (tI + 1) & 1);
            cp_commit();
        }
        const float* a = sA[tI & 1];
        const float* b = sB[tI & 1];
        #pragma unroll
        for (int ks = 0; ks < 2; ks++) {
            int kk = ks * 8;
            uint32_t af[MI][4];
            uint32_t bf[NJ][2];
            #pragma unroll
            for (int i = 0; i < MI; i++) {
                int r = wm0 + i * 16 + g;
                af[i][0] = __float_as_uint(a[r * ASTR + kk + t]);
                af[i][1] = __float_as_uint(a[(r + 8) * ASTR + kk + t]);
                af[i][2] = __float_as_uint(a[r * ASTR + kk + t + 4]);
                af[i][3] = __float_as_uint(a[(r + 8) * ASTR + kk + t + 4]);
            }
            #pragma unroll
            for (int j = 0; j < NJ; j++) {
                int n = wn0 + j * 8 + g;
                if (TB) {
                    bf[j][0] = __float_as_uint(b[n * BSTR + kk + t]);
                    bf[j][1] = __float_as_uint(b[n * BSTR + kk + t + 4]);
                } else {
                    bf[j][0] = __float_as_uint(b[(kk + t) * BSTR + n]);
                    bf[j][1] = __float_as_uint(b[(kk + t + 4) * BSTR + n]);
                }
            }
            #pragma unroll
            for (int i = 0; i < MI; i++)
                #pragma unroll
                for (int j = 0; j < NJ; j++)
                    mma_tf32(acc[i][j], af[i], bf[j]);
        }
        __syncthreads();
    }

    #pragma unroll
    for (int i = 0; i < MI; i++) {
        #pragma unroll
        for (int j = 0; j < NJ; j++) {
            int r = row0 + wm0 + i * 16 + g;
            int c = n0 + wn0 + j * 8 + t * 2;
            float2 v0 = make_float2(acc[i][j][0] * alpha, acc[i][j][1] * alpha);
            float2 v1 = make_float2(acc[i][j][2] * alpha, acc[i][j][3] * alpha);
            *(float2*)(C + (size_t)r * ldc + c) = v0;
            *(float2*)(C + (size_t)(r + 8) * ldc + c) = v1;
        }
    }
}

// ---------------- RoPE (in-place on q,k inside g_qkv) ------------------------
__global__ void rope_kernel(const float* __restrict__ cosb, const float* __restrict__ sinb) {
    int s = blockIdx.x, n = blockIdx.y;
    int tid = threadIdx.x;            // 512
    int h = tid >> 5, j = tid & 31;
    float c0 = cosb[s * HDIM + j],      s0 = sinb[s * HDIM + j];
    float c1 = cosb[s * HDIM + j + 32], s1 = sinb[s * HDIM + j + 32];
    float* row = g_qkv + ((size_t)n * SEQ + s) * (3 * DM);
    float* q = row + h * HDIM;
    float qa = q[j], qb = q[j + 32];
    q[j]      = qa * c0 - qb * s0;
    q[j + 32] = qb * c1 + qa * s1;
    float* k = row + DM + h * HDIM;
    float ka = k[j], kb = k[j + 32];
    k[j]      = ka * c0 - kb * s0;
    k[j + 32] = kb * c1 + ka * s1;
}

// ---------------- flash attention: QK^T -> online softmax -> P@V -------------
// grid (SEQ/64, NSAMP*HN), 128 threads (4 warps x 16 q-rows).
#define QSTR 68
#define KSTR 68
#define VSTR 72
#define FLASH_SMEM ((64 * QSTR + 2 * 64 * KSTR + 2 * 64 * VSTR) * 4)

__global__ __launch_bounds__(128) void flash_kernel() {
    extern __shared__ float sm[];
    float* Qs = sm;                                // 64 x QSTR
    float* Ks = sm + 64 * QSTR;                    // 2 x 64 x KSTR
    float* Vs = sm + 64 * QSTR + 2 * 64 * KSTR;    // 2 x 64 x VSTR

    int nh = blockIdx.y;
    int n = nh >> 4, h = nh & 15;
    int q0 = blockIdx.x * 64;
    const float* qbase = g_qkv + (size_t)n * SEQ * (3 * DM) + h * HDIM;
    const float* kbase = qbase + DM;
    const float* vbase = qbase + 2 * DM;

    int tid = threadIdx.x, lane = tid & 31, wid = tid >> 5;
    int g = lane >> 2, t = lane & 3;
    int wm0 = wid * 16;

    uint32_t su = (uint32_t)__cvta_generic_to_shared(sm);
    uint32_t qsu = su;
    uint32_t ksu = su + 64 * QSTR * 4;
    uint32_t vsu = su + (64 * QSTR + 2 * 64 * KSTR) * 4;

    // ---- initial loads: Q tile + K/V tile 0
    #pragma unroll
    for (int p = 0; p < 8; p++) {
        int i = tid + p * 128;
        int row = i >> 4, c4 = (i & 15) * 4;
        cp16(qsu + (uint32_t)(row * QSTR + c4) * 4,
             qbase + (size_t)(q0 + row) * (3 * DM) + c4);
        cp16(ksu + (uint32_t)(row * KSTR + c4) * 4,
             kbase + (size_t)row * (3 * DM) + c4);
        cp16(vsu + (uint32_t)(row * VSTR + c4) * 4,
             vbase + (size_t)row * (3 * DM) + c4);
    }
    cp_commit();
    cp_wait0();
    __syncthreads();

    // ---- Q fragments in registers (warp rows wm0..wm0+15, K-dim 64)
    uint32_t qf[8][4];
    #pragma unroll
    for (int kc = 0; kc < 8; kc++) {
        int r = wm0 + g;
        qf[kc][0] = __float_as_uint(Qs[r * QSTR + kc * 8 + t]);
        qf[kc][1] = __float_as_uint(Qs[(r + 8) * QSTR + kc * 8 + t]);
        qf[kc][2] = __float_as_uint(Qs[r * QSTR + kc * 8 + t + 4]);
        qf[kc][3] = __float_as_uint(Qs[(r + 8) * QSTR + kc * 8 + t + 4]);
    }

    float m0 = -INFINITY, m1 = -INFINITY, l0 = 0.f, l1 = 0.f;
    float oa[8][4];
    #pragma unroll
    for (int j = 0; j < 8; j++)
        #pragma unroll
        for (int q = 0; q < 4; q++) oa[j][q] = 0.f;

    const int NT = SEQ / 64;   // 16
    for (int it = 0; it < NT; it++) {
        int buf = it & 1;
        if (it + 1 < NT) {
            int kv = (it + 1) * 64;
            int ob = buf ^ 1;
            #pragma unroll
            for (int p = 0; p < 8; p++) {
                int i = tid + p * 128;
                int row = i >> 4, c4 = (i & 15) * 4;
                cp16(ksu + (uint32_t)(ob * 64 * KSTR + row * KSTR + c4) * 4,
                     kbase + (size_t)(kv + row) * (3 * DM) + c4);
                cp16(vsu + (uint32_t)(ob * 64 * VSTR + row * VSTR + c4) * 4,
                     vbase + (size_t)(kv + row) * (3 * DM) + c4);
            }
            cp_commit();
        }
        const float* kb = Ks + buf * 64 * KSTR;
        const float* vb = Vs + buf * 64 * VSTR;

        // ---- S = Q K^T
        float sacc[8][4];
        #pragma unroll
        for (int j = 0; j < 8; j++)
            #pragma unroll
            for (int q = 0; q < 4; q++) sacc[j][q] = 0.f;

        #pragma unroll
        for (int kc = 0; kc < 8; kc++) {
            #pragma unroll
            for (int nt = 0; nt < 8; nt++) {
                uint32_t bf[2];
                int nrow = nt * 8 + g;
                bf[0] = __float_as_uint(kb[nrow * KSTR + kc * 8 + t]);
                bf[1] = __float_as_uint(kb[nrow * KSTR + kc * 8 + t + 4]);
                mma_tf32(sacc[nt], qf[kc], bf);
            }
        }

        // ---- online softmax (scale 1/8)
        float rm0 = -INFINITY, rm1 = -INFINITY;
        #pragma unroll
        for (int nt = 0; nt < 8; nt++) {
            #pragma unroll
            for (int q = 0; q < 4; q++) sacc[nt][q] *= 0.125f;
            rm0 = fmaxf(rm0, fmaxf(sacc[nt][0], sacc[nt][1]));
            rm1 = fmaxf(rm1, fmaxf(sacc[nt][2], sacc[nt][3]));
        }
        rm0 = fmaxf(rm0, __shfl_xor_sync(0xFFFFFFFFu, rm0, 1));
        rm0 = fmaxf(rm0, __shfl_xor_sync(0xFFFFFFFFu, rm0, 2));
        rm1 = fmaxf(rm1, __shfl_xor_sync(0xFFFFFFFFu, rm1, 1));
        rm1 = fmaxf(rm1, __shfl_xor_sync(0xFFFFFFFFu, rm1, 2));
        float mn0 = fmaxf(m0, rm0), mn1 = fmaxf(m1, rm1);
        float c0 = __expf(m0 - mn0), c1 = __expf(m1 - mn1);
        float ls0 = 0.f, ls1 = 0.f;
        #pragma unroll
        for (int nt = 0; nt < 8; nt++) {
            sacc[nt][0] = __expf(sacc[nt][0] - mn0);
            sacc[nt][1] = __expf(sacc[nt][1] - mn0);
            sacc[nt][2] = __expf(sacc[nt][2] - mn1);
            sacc[nt][3] = __expf(sacc[nt][3] - mn1);
            ls0 += sacc[nt][0] + sacc[nt][1];
            ls1 += sacc[nt][2] + sacc[nt][3];
        }
        ls0 += __shfl_xor_sync(0xFFFFFFFFu, ls0, 1);
        ls0 += __shfl_xor_sync(0xFFFFFFFFu, ls0, 2);
        ls1 += __shfl_xor_sync(0xFFFFFFFFu, ls1, 1);
        ls1 += __shfl_xor_sync(0xFFFFFFFFu, ls1, 2);
        l0 = l0 * c0 + ls0;
        l1 = l1 * c1 + ls1;
        m0 = mn0; m1 = mn1;
        #pragma unroll
        for (int j = 0; j < 8; j++) {
            oa[j][0] *= c0; oa[j][1] *= c0;
            oa[j][2] *= c1; oa[j][3] *= c1;
        }

        // ---- O += P @ V  (re-layout P fragments via intra-quad shuffles)
        int srcA = (lane & ~3) | (t >> 1);
        int srcB = srcA + 2;
        bool odd = (t & 1);
        #pragma unroll
        for (int kc = 0; kc < 8; kc++) {
            float u0 = __shfl_sync(0xFFFFFFFFu, sacc[kc][0], srcA);
            float u1 = __shfl_sync(0xFFFFFFFFu, sacc[kc][1], srcA);
            float w0 = __shfl_sync(0xFFFFFFFFu, sacc[kc][0], srcB);
            float w1 = __shfl_sync(0xFFFFFFFFu, sacc[kc][1], srcB);
            float v0 = __shfl_sync(0xFFFFFFFFu, sacc[kc][2], srcA);
            float v1 = __shfl_sync(0xFFFFFFFFu, sacc[kc][3], srcA);
            float x0 = __shfl_sync(0xFFFFFFFFu, sacc[kc][2], srcB);
            float x1 = __shfl_sync(0xFFFFFFFFu, sacc[kc][3], srcB);
            uint32_t af[4];
            af[0] = __float_as_uint(odd ? u1 : u0);   // P(g,   t)
            af[1] = __float_as_uint(odd ? v1 : v0);   // P(g+8, t)
            af[2] = __float_as_uint(odd ? w1 : w0);   // P(g,   t+4)
            af[3] = __float_as_uint(odd ? x1 : x0);   // P(g+8, t+4)
            #pragma unroll
            for (int jn = 0; jn < 8; jn++) {
                uint32_t bf[2];
                bf[0] = __float_as_uint(vb[(kc * 8 + t) * VSTR + jn * 8 + g]);
                bf[1] = __float_as_uint(vb[(kc * 8 + t + 4) * VSTR + jn * 8 + g]);
                mma_tf32(oa[jn], af, bf);
            }
        }

        cp_wait0();
        __syncthreads();
    }

    // ---- write O / l to g_ctx
    float inv0 = 1.0f / l0, inv1 = 1.0f / l1;
    int grow0 = q0 + wm0 + g;
    float* cbase = g_ctx + (size_t)n * SEQ * DM + h * HDIM;
    #pragma unroll
    for (int jn = 0; jn < 8; jn++) {
        int col = jn * 8 + 2 * t;
        *(float2*)(cbase + (size_t)grow0 * DM + col) =
            make_float2(oa[jn][0] * inv0, oa[jn][1] * inv0);
        *(float2*)(cbase + (size_t)(grow0 + 8) * DM + col) =
            make_float2(oa[jn][2] * inv1, oa[jn][3] * inv1);
    }
}

// ---------------- residual + rmsnorm ------------------------------------------
__global__ void resid_rms_kernel(const float* __restrict__ hidden) {
    __shared__ float sh[32];
    int ns = blockIdx.x;
    int n = ns >> 10, s = ns & 1023;
    const float* xr = hidden + ((size_t)(n >> 1) * SEQ + s) * DM;
    const float* ar = g_ao + ((size_t)n * SEQ + s) * DM;
    float* o = g_x1 + ((size_t)n * SEQ + s) * DM;
    int tid = threadIdx.x;
    float y[4];
    float ss = 0.f;
    #pragma unroll
    for (int i = 0; i < 4; i++) {
        int d = tid + i * 256;
        y[i] = xr[d] + ar[d];
        ss = fmaf(y[i], y[i], ss);
    }
    ss = block_reduce_sum(ss, sh);
    float scale = rsqrtf(ss * (1.0f / (float)DM) + EPS);
    #pragma unroll
    for (int i = 0; i < 4; i++) o[tid + i * 256] = y[i] * scale;
}

// ---------------- silu(gate) * up ----------------------------------------------
__global__ void act_kernel() {
    size_t idx = (size_t)blockIdx.x * blockDim.x + threadIdx.x;
    size_t r = idx / INTER;
    int i = (int)(idx % INTER);
    float g = g_gu[r * (2 * INTER) + i];
    float u = g_gu[r * (2 * INTER) + INTER + i];
    float sg = g / (1.0f + __expf(-g));
    g_act[idx] = sg * u;
}

// ---------------- final: rmsnorm(x1 + mlp), weighted top-2 combine -------------
__global__ void final_kernel(float* __restrict__ out) {
    __shared__ float sh[32];
    int bs = blockIdx.x;
    int b = bs >> 10, s = bs & 1023;
    int tid = threadIdx.x;
    int n0 = 2 * b, n1 = 2 * b + 1;
    size_t base0 = ((size_t)n0 * SEQ + s) * DM;
    size_t base1 = ((size_t)n1 * SEQ + s) * DM;
    float y0[4], y1[4];
    float ss0 = 0.f, ss1 = 0.f;
    #pragma unroll
    for (int i = 0; i < 4; i++) {
        int d = tid + i * 256;
        y0[i] = g_x1[base0 + d] + g_mlp[base0 + d];
        y1[i] = g_x1[base1 + d] + g_mlp[base1 + d];
        ss0 = fmaf(y0[i], y0[i], ss0);
        ss1 = fmaf(y1[i], y1[i], ss1);
    }
    ss0 = block_reduce_sum(ss0, sh);
    ss1 = block_reduce_sum(ss1, sh);
    float r0 = rsqrtf(ss0 * (1.0f / (float)DM) + EPS) * g_w[n0];
    float r1 = rsqrtf(ss1 * (1.0f / (float)DM) + EPS) * g_w[n1];
    float* orow = out + ((size_t)b * SEQ + s) * DM;
    #pragma unroll
    for (int i = 0; i < 4; i++) {
        int d = tid + i * 256;
        orow[d] = y0[i] * r0 + y1[i] * r1;
    }
}

// ---------------- host launcher --------------------------------------------------
extern "C" void kernel_launch(void* const* d_in, const int* in_sizes, int n_in,
                              void* d_out, int out_size) {
    const float* hidden = (const float*)d_in[0];
    const float* cosb   = (const float*)d_in[1];
    const float* sinb   = (const float*)d_in[2];
    const float* Wr     = (const float*)d_in[3];
    const float* temp   = (const float*)d_in[4];
    const float* Wqkv   = (const float*)d_in[5];
    const float* Wo     = (const float*)d_in[6];
    const float* Wgu    = (const float*)d_in[7];
    const float* Wd     = (const float*)d_in[8];
    float* out = (float*)d_out;

    float *p_qkv, *p_ctx, *p_ao, *p_x1, *p_gu, *p_act, *p_mlp;
    cudaGetSymbolAddress((void**)&p_qkv, g_qkv);
    cudaGetSymbolAddress((void**)&p_ctx, g_ctx);
    cudaGetSymbolAddress((void**)&p_ao,  g_ao);
    cudaGetSymbolAddress((void**)&p_x1,  g_x1);
    cudaGetSymbolAddress((void**)&p_gu,  g_gu);
    cudaGetSymbolAddress((void**)&p_act, g_act);
    cudaGetSymbolAddress((void**)&p_mlp, g_mlp);

    cudaFuncSetAttribute(flash_kernel,
                         cudaFuncAttributeMaxDynamicSharedMemorySize, FLASH_SMEM);

    // routing
    mean1_kernel<<<dim3(BATCH, 16), 256>>>(hidden);
    mean2_kernel<<<BATCH, 256>>>();
    routing_kernel<<<1, 1024>>>(Wr, temp, out + (size_t)BATCH * SEQ * DM);

    // qkv = x @ Wqkv[e]   (M=1024, N=3072, K=1024)
    mma_gemm<128, 128, 2, 4, false><<<dim3(3072 / 128, SEQ / 128, NSAMP), 256>>>(
        hidden, Wqkv, p_qkv, SEQ, 3 * DM, DM, DM, 3 * DM, 3 * DM,
        2, (long long)SEQ * DM, 0, 0, 0,
        2LL * SEQ * 3 * DM, (long long)SEQ * 3 * DM,
        1, (long long)DM * 3 * DM, 1.0f);

    // rope in-place
    rope_kernel<<<dim3(SEQ, NSAMP), 512>>>(cosb, sinb);

    // fused attention -> g_ctx
    flash_kernel<<<dim3(SEQ / 64, NSAMP * HN), 128, FLASH_SMEM>>>();

    // attn_out = ctx @ Wo[e]
    mma_gemm<128, 128, 2, 4, false><<<dim3(DM / 128, SEQ / 128, NSAMP), 256>>>(
        p_ctx, Wo, p_ao, SEQ, DM, DM, DM, DM, DM,
        1, (long long)SEQ * DM, 0, 0, 0,
        (long long)SEQ * DM, 0,
        1, (long long)DM * DM, 1.0f);

    // x1 = rmsnorm(x + attn_out)
    resid_rms_kernel<<<NSAMP * SEQ, 256>>>(hidden);

    // gu = x1 @ Wgu[e]
    mma_gemm<128, 128, 2, 4, false><<<dim3(2 * INTER / 128, SEQ / 128, NSAMP), 256>>>(
        p_x1, Wgu, p_gu, SEQ, 2 * INTER, DM, DM, 2 * INTER, 2 * INTER,
        1, (long long)SEQ * DM, 0, 0, 0,
        (long long)SEQ * 2 * INTER, 0,
        1, (long long)DM * 2 * INTER, 1.0f);

    // act = silu(gate) * up
    act_kernel<<<(NSAMP * SEQ * INTER) / 256, 256>>>();

    // mlp = act @ Wd[e]
    mma_gemm<128, 128, 2, 4, false><<<dim3(DM / 128, SEQ / 128, NSAMP), 256>>>(
        p_act, Wd, p_mlp, SEQ, DM, INTER, INTER, DM, DM,
        1, (long long)SEQ * INTER, 0, 0, 0,
        (long long)SEQ * DM, 0,
        1, (long long)INTER * DM, 1.0f);

    // out = sum of weighted rmsnorm(x1 + mlp)
    final_kernel<<<BATCH * SEQ, 256>>>(out);
}

// round 5
// speedup vs baseline: 3.6767x; 1.0107x over previous
#include <cuda_runtime.h>
#include <math.h>
#include <stdint.h>

#define SEQ   1024
#define DM    1024
#define HN    16
#define HDIM  64
#define NSAMP 8
#define INTER 768
#define BATCH 4
#define EPS   1e-5f

// ---------------- scratch (device globals; no allocations allowed) ----------
__device__ float g_hsmean[BATCH * DM];
__device__ float g_partial[BATCH * 16 * DM];
__device__ int   g_expert[NSAMP];
__device__ float g_w[NSAMP];
__device__ float g_qkv[(size_t)NSAMP * SEQ * 3 * DM];        // 96 MB
__device__ float g_ctx[(size_t)NSAMP * SEQ * DM];            // 32 MB
__device__ float g_ao[(size_t)NSAMP * SEQ * DM];             // 32 MB
__device__ float g_x1[(size_t)NSAMP * SEQ * DM];             // 32 MB
__device__ float g_gu[(size_t)NSAMP * SEQ * 2 * INTER];      // 48 MB
__device__ float g_act[(size_t)NSAMP * SEQ * INTER];         // 24 MB
__device__ float g_mlp[(size_t)NSAMP * SEQ * DM];            // 32 MB

// ---------------- small helpers ----------------------------------------------
__device__ __forceinline__ float block_reduce_sum(float v, float* sh) {
    int tid = threadIdx.x;
    #pragma unroll
    for (int o = 16; o; o >>= 1) v += __shfl_down_sync(0xFFFFFFFFu, v, o);
    if ((tid & 31) == 0) sh[tid >> 5] = v;
    __syncthreads();
    float r = 0.f;
    if (tid < 32) {
        float x = (tid < (int)(blockDim.x >> 5)) ? sh[tid] : 0.f;
        #pragma unroll
        for (int o = 16; o; o >>= 1) x += __shfl_down_sync(0xFFFFFFFFu, x, o);
        if (tid == 0) sh[0] = x;
    }
    __syncthreads();
    r = sh[0];
    __syncthreads();
    return r;
}

__device__ __forceinline__ void mma_tf32(float* d, const uint32_t* a, const uint32_t* b) {
    asm volatile(
        "mma.sync.aligned.m16n8k8.row.col.f32.tf32.tf32.f32 "
        "{%0,%1,%2,%3},{%4,%5,%6,%7},{%8,%9},{%0,%1,%2,%3};"
        : "+f"(d[0]), "+f"(d[1]), "+f"(d[2]), "+f"(d[3])
        : "r"(a[0]), "r"(a[1]), "r"(a[2]), "r"(a[3]), "r"(b[0]), "r"(b[1]));
}

__device__ __forceinline__ void cp16(uint32_t s, const void* g) {
    asm volatile("cp.async.cg.shared.global [%0], [%1], 16;" :: "r"(s), "l"(g));
}
__device__ __forceinline__ void cp_commit() {
    asm volatile("cp.async.commit_group;" ::: "memory");
}
__device__ __forceinline__ void cp_wait0() {
    asm volatile("cp.async.wait_group 0;" ::: "memory");
}
__device__ __forceinline__ void cp_wait1() {
    asm volatile("cp.async.wait_group 1;" ::: "memory");
}
__device__ __forceinline__ void cp_wait2() {
    asm volatile("cp.async.wait_group 2;" ::: "memory");
}

// ---------------- routing ----------------------------------------------------
__global__ void mean1_kernel(const float* __restrict__ hidden) {
    int b = blockIdx.x, c = blockIdx.y;
    int tid = threadIdx.x;
    float acc[4] = {0.f, 0.f, 0.f, 0.f};
    for (int s = c * 64; s < c * 64 + 64; s++) {
        const float* row = hidden + ((size_t)b * SEQ + s) * DM;
        #pragma unroll
        for (int i = 0; i < 4; i++) acc[i] += row[tid + i * 256];
    }
    #pragma unroll
    for (int i = 0; i < 4; i++)
        g_partial[((size_t)b * 16 + c) * DM + tid + i * 256] = acc[i];
}

__global__ void mean2_kernel() {
    int b = blockIdx.x;
    int tid = threadIdx.x;
    #pragma unroll
    for (int i = 0; i < 4; i++) {
        int d = tid + i * 256;
        float s = 0.f;
        for (int c = 0; c < 16; c++) s += g_partial[((size_t)b * 16 + c) * DM + d];
        g_hsmean[b * DM + d] = s * (1.0f / (float)SEQ);
    }
}

__global__ void routing_kernel(const float* __restrict__ Wr,
                               const float* __restrict__ temperature,
                               float* __restrict__ out_logits) {
    int tid = threadIdx.x;          // 1024
    int w = tid >> 5, lane = tid & 31;
    int b = w >> 3, c = w & 7;
    float s = 0.f;
    for (int d = lane; d < DM; d += 32)
        s += g_hsmean[b * DM + d] * Wr[c * DM + d];
    #pragma unroll
    for (int o = 16; o; o >>= 1) s += __shfl_down_sync(0xFFFFFFFFu, s, o);
    __shared__ float logits[32];
    if (lane == 0) logits[w] = s;
    __syncthreads();
    if (tid < BATCH) {
        float t = fminf(fmaxf(temperature[0], 0.1f), 10.0f);
        float lv[8];
        #pragma unroll
        for (int cc = 0; cc < 8; cc++) {
            lv[cc] = logits[tid * 8 + cc] / t;
            out_logits[tid * 8 + cc] = lv[cc];
        }
        int i0 = 0;
        #pragma unroll
        for (int cc = 1; cc < 8; cc++) if (lv[cc] > lv[i0]) i0 = cc;
        int i1 = -1;
        #pragma unroll
        for (int cc = 0; cc < 8; cc++) {
            if (cc == i0) continue;
            if (i1 < 0 || lv[cc] > lv[i1]) i1 = cc;
        }
        float e = expf(lv[i1] - lv[i0]);
        g_expert[2 * tid]     = i0;
        g_expert[2 * tid + 1] = i1;
        g_w[2 * tid]     = 1.0f / (1.0f + e);
        g_w[2 * tid + 1] = e / (1.0f + e);
    }
}

// ---------------- generic tf32 tensor-core GEMM (4-stage cp.async ring) -------
#define GSTAGES 4
template<int BM, int BN, int WPM, int WPN, bool TB>
__global__ __launch_bounds__(256) void mma_gemm(
    const float* __restrict__ Ab, const float* __restrict__ Bb, float* __restrict__ Cb,
    int M, int N, int K, int lda, int ldb, int ldc,
    int Z0, long long sa1, long long sa0, long long sb1, long long sb0,
    long long sc1, long long sc0, int useExpert, long long sbExp, float alpha)
{
    constexpr int BK   = 16;
    constexpr int ASTR = BK + 4;
    constexpr int BSTR = TB ? (BK + 4) : (BN + 8);
    constexpr int BROWS = TB ? BN : BK;
    constexpr int WM = BM / WPM, WN = BN / WPN;
    constexpr int MI = WM / 16, NJ = WN / 8;
    constexpr int ACH = BM * 4 / 256;
    constexpr int BCH = BN * 4 / 256;
    constexpr int ASZ = BM * ASTR;
    constexpr int BSZ = BROWS * BSTR;

    extern __shared__ float dynsm[];
    float* sA = dynsm;                       // GSTAGES x ASZ
    float* sB = dynsm + GSTAGES * ASZ;       // GSTAGES x BSZ

    int z = blockIdx.z;
    int z1 = z / Z0, z0 = z % Z0;
    const float* A = Ab + z1 * sa1 + z0 * sa0;
    const float* B = useExpert ? (Bb + (long long)g_expert[z] * sbExp)
                               : (Bb + z1 * sb1 + z0 * sb0);
    float* C = Cb + z1 * sc1 + z0 * sc0;

    int row0 = blockIdx.y * BM;
    int n0   = blockIdx.x * BN;
    int tid = threadIdx.x, lane = tid & 31, wid = tid >> 5;
    int wm0 = (wid % WPM) * WM;
    int wn0 = (wid / WPM) * WN;
    int g = lane >> 2, t = lane & 3;

    uint32_t sAu = (uint32_t)__cvta_generic_to_shared(sA);
    uint32_t sBu = (uint32_t)__cvta_generic_to_shared(sB);

    float acc[MI][NJ][4];
    #pragma unroll
    for (int i = 0; i < MI; i++)
        #pragma unroll
        for (int j = 0; j < NJ; j++)
            #pragma unroll
            for (int q = 0; q < 4; q++) acc[i][j][q] = 0.f;

    auto load_tiles = [&](int k0, int buf) {
        #pragma unroll
        for (int p = 0; p < ACH; p++) {
            int i = tid + p * 256;
            int m = i >> 2, kc = (i & 3) * 4;
            cp16(sAu + (uint32_t)(buf * ASZ + m * ASTR + kc) * 4,
                 A + (size_t)(row0 + m) * lda + k0 + kc);
        }
        if (TB) {
            #pragma unroll
            for (int p = 0; p < BCH; p++) {
                int i = tid + p * 256;
                int n = i >> 2, kc = (i & 3) * 4;
                cp16(sBu + (uint32_t)(buf * BSZ + n * BSTR + kc) * 4,
                     B + (size_t)(n0 + n) * ldb + k0 + kc);
            }
        } else {
            #pragma unroll
            for (int p = 0; p < BCH; p++) {
                int i = tid + p * 256;
                int k = i / (BN / 4), nc = (i % (BN / 4)) * 4;
                cp16(sBu + (uint32_t)(buf * BSZ + k * BSTR + nc) * 4,
                     B + (size_t)(k0 + k) * ldb + n0 + nc);
            }
        }
    };

    int NT = K / BK;
    #pragma unroll
    for (int p = 0; p < GSTAGES - 1; p++) {
        if (p < NT) { load_tiles(p * BK, p); cp_commit(); }
    }

    for (int tI = 0; tI < NT; ++tI) {
        int rem = NT - 1 - tI;
        if (rem >= 2) cp_wait2();
        else if (rem == 1) cp_wait1();
        else cp_wait0();
        __syncthreads();
        if (tI + GSTAGES - 1 < NT) {
            load_tiles((tI + GSTAGES - 1) * BK, (tI + GSTAGES - 1) & (GSTAGES - 1));
            cp_commit();
        }
        const float* a = sA + (tI & (GSTAGES - 1)) * ASZ;
        const float* b = sB + (tI & (GSTAGES - 1)) * BSZ;
        #pragma unroll
        for (int ks = 0; ks < 2; ks++) {
            int kk = ks * 8;
            uint32_t af[MI][4];
            uint32_t bf[NJ][2];
            #pragma unroll
            for (int i = 0; i < MI; i++) {
                int r = wm0 + i * 16 + g;
                af[i][0] = __float_as_uint(a[r * ASTR + kk + t]);
                af[i][1] = __float_as_uint(a[(r + 8) * ASTR + kk + t]);
                af[i][2] = __float_as_uint(a[r * ASTR + kk + t + 4]);
                af[i][3] = __float_as_uint(a[(r + 8) * ASTR + kk + t + 4]);
            }
            #pragma unroll
            for (int j = 0; j < NJ; j++) {
                int n = wn0 + j * 8 + g;
                if (TB) {
                    bf[j][0] = __float_as_uint(b[n * BSTR + kk + t]);
                    bf[j][1] = __float_as_uint(b[n * BSTR + kk + t + 4]);
                } else {
                    bf[j][0] = __float_as_uint(b[(kk + t) * BSTR + n]);
                    bf[j][1] = __float_as_uint(b[(kk + t + 4) * BSTR + n]);
                }
            }
            #pragma unroll
            for (int i = 0; i < MI; i++)
                #pragma unroll
                for (int j = 0; j < NJ; j++)
                    mma_tf32(acc[i][j], af[i], bf[j]);
        }
    }

    #pragma unroll
    for (int i = 0; i < MI; i++) {
        #pragma unroll
        for (int j = 0; j < NJ; j++) {
            int r = row0 + wm0 + i * 16 + g;
            int c = n0 + wn0 + j * 8 + t * 2;
            float2 v0 = make_float2(acc[i][j][0] * alpha, acc[i][j][1] * alpha);
            float2 v1 = make_float2(acc[i][j][2] * alpha, acc[i][j][3] * alpha);
            *(float2*)(C + (size_t)r * ldc + c) = v0;
            *(float2*)(C + (size_t)(r + 8) * ldc + c) = v1;
        }
    }
}

#define GEMM_SMEM (GSTAGES * (128 * 20 + 16 * 136) * 4)

// ---------------- RoPE (in-place on q,k inside g_qkv) ------------------------
__global__ void rope_kernel(const float* __restrict__ cosb, const float* __restrict__ sinb) {
    int s = blockIdx.x, n = blockIdx.y;
    int tid = threadIdx.x;            // 512
    int h = tid >> 5, j = tid & 31;
    float c0 = cosb[s * HDIM + j],      s0 = sinb[s * HDIM + j];
    float c1 = cosb[s * HDIM + j + 32], s1 = sinb[s * HDIM + j + 32];
    float* row = g_qkv + ((size_t)n * SEQ + s) * (3 * DM);
    float* q = row + h * HDIM;
    float qa = q[j], qb = q[j + 32];
    q[j]      = qa * c0 - qb * s0;
    q[j + 32] = qb * c1 + qa * s1;
    float* k = row + DM + h * HDIM;
    float ka = k[j], kb = k[j + 32];
    k[j]      = ka * c0 - kb * s0;
    k[j + 32] = kb * c1 + ka * s1;
}

// ---------------- flash attention: QK^T -> online softmax -> P@V -------------
#define QSTR 68
#define KSTR 68
#define VSTR 72
#define FLASH_SMEM ((64 * QSTR + 2 * 64 * KSTR + 2 * 64 * VSTR) * 4)

__global__ __launch_bounds__(128) void flash_kernel() {
    extern __shared__ float sm[];
    float* Qs = sm;
    float* Ks = sm + 64 * QSTR;
    float* Vs = sm + 64 * QSTR + 2 * 64 * KSTR;

    int nh = blockIdx.y;
    int n = nh >> 4, h = nh & 15;
    int q0 = blockIdx.x * 64;
    const float* qbase = g_qkv + (size_t)n * SEQ * (3 * DM) + h * HDIM;
    const float* kbase = qbase + DM;
    const float* vbase = qbase + 2 * DM;

    int tid = threadIdx.x, lane = tid & 31, wid = tid >> 5;
    int g = lane >> 2, t = lane & 3;
    int wm0 = wid * 16;

    uint32_t su = (uint32_t)__cvta_generic_to_shared(sm);
    uint32_t qsu = su;
    uint32_t ksu = su + 64 * QSTR * 4;
    uint32_t vsu = su + (64 * QSTR + 2 * 64 * KSTR) * 4;

    #pragma unroll
    for (int p = 0; p < 8; p++) {
        int i = tid + p * 128;
        int row = i >> 4, c4 = (i & 15) * 4;
        cp16(qsu + (uint32_t)(row * QSTR + c4) * 4,
             qbase + (size_t)(q0 + row) * (3 * DM) + c4);
        cp16(ksu + (uint32_t)(row * KSTR + c4) * 4,
             kbase + (size_t)row * (3 * DM) + c4);
        cp16(vsu + (uint32_t)(row * VSTR + c4) * 4,
             vbase + (size_t)row * (3 * DM) + c4);
    }
    cp_commit();
    cp_wait0();
    __syncthreads();

    uint32_t qf[8][4];
    #pragma unroll
    for (int kc = 0; kc < 8; kc++) {
        int r = wm0 + g;
        qf[kc][0] = __float_as_uint(Qs[r * QSTR + kc * 8 + t]);
        qf[kc][1] = __float_as_uint(Qs[(r + 8) * QSTR + kc * 8 + t]);
        qf[kc][2] = __float_as_uint(Qs[r * QSTR + kc * 8 + t + 4]);
        qf[kc][3] = __float_as_uint(Qs[(r + 8) * QSTR + kc * 8 + t + 4]);
    }

    float m0 = -INFINITY, m1 = -INFINITY, l0 = 0.f, l1 = 0.f;
    float oa[8][4];
    #pragma unroll
    for (int j = 0; j < 8; j++)
        #pragma unroll
        for (int q = 0; q < 4; q++) oa[j][q] = 0.f;

    const int NT = SEQ / 64;
    for (int it = 0; it < NT; it++) {
        int buf = it & 1;
        if (it + 1 < NT) {
            int kv = (it + 1) * 64;
            int ob = buf ^ 1;
            #pragma unroll
            for (int p = 0; p < 8; p++) {
                int i = tid + p * 128;
                int row = i >> 4, c4 = (i & 15) * 4;
                cp16(ksu + (uint32_t)(ob * 64 * KSTR + row * KSTR + c4) * 4,
                     kbase + (size_t)(kv + row) * (3 * DM) + c4);
                cp16(vsu + (uint32_t)(ob * 64 * VSTR + row * VSTR + c4) * 4,
                     vbase + (size_t)(kv + row) * (3 * DM) + c4);
            }
            cp_commit();
        }
        const float* kb = Ks + buf * 64 * KSTR;
        const float* vb = Vs + buf * 64 * VSTR;

        float sacc[8][4];
        #pragma unroll
        for (int j = 0; j < 8; j++)
            #pragma unroll
            for (int q = 0; q < 4; q++) sacc[j][q] = 0.f;

        #pragma unroll
        for (int kc = 0; kc < 8; kc++) {
            #pragma unroll
            for (int nt = 0; nt < 8; nt++) {
                uint32_t bf[2];
                int nrow = nt * 8 + g;
                bf[0] = __float_as_uint(kb[nrow * KSTR + kc * 8 + t]);
                bf[1] = __float_as_uint(kb[nrow * KSTR + kc * 8 + t + 4]);
                mma_tf32(sacc[nt], qf[kc], bf);
            }
        }

        float rm0 = -INFINITY, rm1 = -INFINITY;
        #pragma unroll
        for (int nt = 0; nt < 8; nt++) {
            #pragma unroll
            for (int q = 0; q < 4; q++) sacc[nt][q] *= 0.125f;
            rm0 = fmaxf(rm0, fmaxf(sacc[nt][0], sacc[nt][1]));
            rm1 = fmaxf(rm1, fmaxf(sacc[nt][2], sacc[nt][3]));
        }
        rm0 = fmaxf(rm0, __shfl_xor_sync(0xFFFFFFFFu, rm0, 1));
        rm0 = fmaxf(rm0, __shfl_xor_sync(0xFFFFFFFFu, rm0, 2));
        rm1 = fmaxf(rm1, __shfl_xor_sync(0xFFFFFFFFu, rm1, 1));
        rm1 = fmaxf(rm1, __shfl_xor_sync(0xFFFFFFFFu, rm1, 2));
        float mn0 = fmaxf(m0, rm0), mn1 = fmaxf(m1, rm1);
        float c0 = __expf(m0 - mn0), c1 = __expf(m1 - mn1);
        float ls0 = 0.f, ls1 = 0.f;
        #pragma unroll
        for (int nt = 0; nt < 8; nt++) {
            sacc[nt][0] = __expf(sacc[nt][0] - mn0);
            sacc[nt][1] = __expf(sacc[nt][1] - mn0);
            sacc[nt][2] = __expf(sacc[nt][2] - mn1);
            sacc[nt][3] = __expf(sacc[nt][3] - mn1);
            ls0 += sacc[nt][0] + sacc[nt][1];
            ls1 += sacc[nt][2] + sacc[nt][3];
        }
        ls0 += __shfl_xor_sync(0xFFFFFFFFu, ls0, 1);
        ls0 += __shfl_xor_sync(0xFFFFFFFFu, ls0, 2);
        ls1 += __shfl_xor_sync(0xFFFFFFFFu, ls1, 1);
        ls1 += __shfl_xor_sync(0xFFFFFFFFu, ls1, 2);
        l0 = l0 * c0 + ls0;
        l1 = l1 * c1 + ls1;
        m0 = mn0; m1 = mn1;
        #pragma unroll
        for (int j = 0; j < 8; j++) {
            oa[j][0] *= c0; oa[j][1] *= c0;
            oa[j][2] *= c1; oa[j][3] *= c1;
        }

        int srcA = (lane & ~3) | (t >> 1);
        int srcB = srcA + 2;
        bool odd = (t & 1);
        #pragma unroll
        for (int kc = 0; kc < 8; kc++) {
            float u0 = __shfl_sync(0xFFFFFFFFu, sacc[kc][0], srcA);
            float u1 = __shfl_sync(0xFFFFFFFFu, sacc[kc][1], srcA);
            float w0 = __shfl_sync(0xFFFFFFFFu, sacc[kc][0], srcB);
            float w1 = __shfl_sync(0xFFFFFFFFu, sacc[kc][1], srcB);
            float v0 = __shfl_sync(0xFFFFFFFFu, sacc[kc][2], srcA);
            float v1 = __shfl_sync(0xFFFFFFFFu, sacc[kc][3], srcA);
            float x0 = __shfl_sync(0xFFFFFFFFu, sacc[kc][2], srcB);
            float x1 = __shfl_sync(0xFFFFFFFFu, sacc[kc][3], srcB);
            uint32_t af[4];
            af[0] = __float_as_uint(odd ? u1 : u0);
            af[1] = __float_as_uint(odd ? v1 : v0);
            af[2] = __float_as_uint(odd ? w1 : w0);
            af[3] = __float_as_uint(odd ? x1 : x0);
            #pragma unroll
            for (int jn = 0; jn < 8; jn++) {
                uint32_t bf[2];
                bf[0] = __float_as_uint(vb[(kc * 8 + t) * VSTR + jn * 8 + g]);
                bf[1] = __float_as_uint(vb[(kc * 8 + t + 4) * VSTR + jn * 8 + g]);
                mma_tf32(oa[jn], af, bf);
            }
        }

        cp_wait0();
        __syncthreads();
    }

    float inv0 = 1.0f / l0, inv1 = 1.0f / l1;
    int grow0 = q0 + wm0 + g;
    float* cbase = g_ctx + (size_t)n * SEQ * DM + h * HDIM;
    #pragma unroll
    for (int jn = 0; jn < 8; jn++) {
        int col = jn * 8 + 2 * t;
        *(float2*)(cbase + (size_t)grow0 * DM + col) =
            make_float2(oa[jn][0] * inv0, oa[jn][1] * inv0);
        *(float2*)(cbase + (size_t)(grow0 + 8) * DM + col) =
            make_float2(oa[jn][2] * inv1, oa[jn][3] * inv1);
    }
}

// ---------------- residual + rmsnorm ------------------------------------------
__global__ void resid_rms_kernel(const float* __restrict__ hidden) {
    __shared__ float sh[32];
    int ns = blockIdx.x;
    int n = ns >> 10, s = ns & 1023;
    const float* xr = hidden + ((size_t)(n >> 1) * SEQ + s) * DM;
    const float* ar = g_ao + ((size_t)n * SEQ + s) * DM;
    float* o = g_x1 + ((size_t)n * SEQ + s) * DM;
    int tid = threadIdx.x;
    float y[4];
    float ss = 0.f;
    #pragma unroll
    for (int i = 0; i < 4; i++) {
        int d = tid + i * 256;
        y[i] = xr[d] + ar[d];
        ss = fmaf(y[i], y[i], ss);
    }
    ss = block_reduce_sum(ss, sh);
    float scale = rsqrtf(ss * (1.0f / (float)DM) + EPS);
    #pragma unroll
    for (int i = 0; i < 4; i++) o[tid + i * 256] = y[i] * scale;
}

// ---------------- silu(gate) * up ----------------------------------------------
__global__ void act_kernel() {
    size_t idx = (size_t)blockIdx.x * blockDim.x + threadIdx.x;
    size_t r = idx / INTER;
    int i = (int)(idx % INTER);
    float g = g_gu[r * (2 * INTER) + i];
    float u = g_gu[r * (2 * INTER) + INTER + i];
    float sg = g / (1.0f + __expf(-g));
    g_act[idx] = sg * u;
}

// ---------------- final: rmsnorm(x1 + mlp), weighted top-2 combine -------------
__global__ void final_kernel(float* __restrict__ out) {
    __shared__ float sh[32];
    int bs = blockIdx.x;
    int b = bs >> 10, s = bs & 1023;
    int tid = threadIdx.x;
    int n0 = 2 * b, n1 = 2 * b + 1;
    size_t base0 = ((size_t)n0 * SEQ + s) * DM;
    size_t base1 = ((size_t)n1 * SEQ + s) * DM;
    float y0[4], y1[4];
    float ss0 = 0.f, ss1 = 0.f;
    #pragma unroll
    for (int i = 0; i < 4; i++) {
        int d = tid + i * 256;
        y0[i] = g_x1[base0 + d] + g_mlp[base0 + d];
        y1[i] = g_x1[base1 + d] + g_mlp[base1 + d];
        ss0 = fmaf(y0[i], y0[i], ss0);
        ss1 = fmaf(y1[i], y1[i], ss1);
    }
    ss0 = block_reduce_sum(ss0, sh);
    ss1 = block_reduce_sum(ss1, sh);
    float r0 = rsqrtf(ss0 * (1.0f / (float)DM) + EPS) * g_w[n0];
    float r1 = rsqrtf(ss1 * (1.0f / (float)DM) + EPS) * g_w[n1];
    float* orow = out + ((size_t)b * SEQ + s) * DM;
    #pragma unroll
    for (int i = 0; i < 4; i++) {
        int d = tid + i * 256;
        orow[d] = y0[i] * r0 + y1[i] * r1;
    }
}

// ---------------- host launcher --------------------------------------------------
extern "C" void kernel_launch(void* const* d_in, const int* in_sizes, int n_in,
                              void* d_out, int out_size) {
    const float* hidden = (const float*)d_in[0];
    const float* cosb   = (const float*)d_in[1];
    const float* sinb   = (const float*)d_in[2];
    const float* Wr     = (const float*)d_in[3];
    const float* temp   = (const float*)d_in[4];
    const float* Wqkv   = (const float*)d_in[5];
    const float* Wo     = (const float*)d_in[6];
    const float* Wgu    = (const float*)d_in[7];
    const float* Wd     = (const float*)d_in[8];
    float* out = (float*)d_out;

    float *p_qkv, *p_ctx, *p_ao, *p_x1, *p_gu, *p_act, *p_mlp;
    cudaGetSymbolAddress((void**)&p_qkv, g_qkv);
    cudaGetSymbolAddress((void**)&p_ctx, g_ctx);
    cudaGetSymbolAddress((void**)&p_ao,  g_ao);
    cudaGetSymbolAddress((void**)&p_x1,  g_x1);
    cudaGetSymbolAddress((void**)&p_gu,  g_gu);
    cudaGetSymbolAddress((void**)&p_act, g_act);
    cudaGetSymbolAddress((void**)&p_mlp, g_mlp);

    cudaFuncSetAttribute(flash_kernel,
                         cudaFuncAttributeMaxDynamicSharedMemorySize, FLASH_SMEM);
    cudaFuncSetAttribute((const void*)mma_gemm<128, 128, 2, 4, false>,
                         cudaFuncAttributeMaxDynamicSharedMemorySize, GEMM_SMEM);

    // routing
    mean1_kernel<<<dim3(BATCH, 16), 256>>>(hidden);
    mean2_kernel<<<BATCH, 256>>>();
    routing_kernel<<<1, 1024>>>(Wr, temp, out + (size_t)BATCH * SEQ * DM);

    // qkv = x @ Wqkv[e]   (M=1024, N=3072, K=1024)
    mma_gemm<128, 128, 2, 4, false><<<dim3(3072 / 128, SEQ / 128, NSAMP), 256, GEMM_SMEM>>>(
        hidden, Wqkv, p_qkv, SEQ, 3 * DM, DM, DM, 3 * DM, 3 * DM,
        2, (long long)SEQ * DM, 0, 0, 0,
        2LL * SEQ * 3 * DM, (long long)SEQ * 3 * DM,
        1, (long long)DM * 3 * DM, 1.0f);

    // rope in-place
    rope_kernel<<<dim3(SEQ, NSAMP), 512>>>(cosb, sinb);

    // fused attention -> g_ctx
    flash_kernel<<<dim3(SEQ / 64, NSAMP * HN), 128, FLASH_SMEM>>>();

    // attn_out = ctx @ Wo[e]
    mma_gemm<128, 128, 2, 4, false><<<dim3(DM / 128, SEQ / 128, NSAMP), 256, GEMM_SMEM>>>(
        p_ctx, Wo, p_ao, SEQ, DM, DM, DM, DM, DM,
        1, (long long)SEQ * DM, 0, 0, 0,
        (long long)SEQ * DM, 0,
        1, (long long)DM * DM, 1.0f);

    // x1 = rmsnorm(x + attn_out)
    resid_rms_kernel<<<NSAMP * SEQ, 256>>>(hidden);

    // gu = x1 @ Wgu[e]
    mma_gemm<128, 128, 2, 4, false><<<dim3(2 * INTER / 128, SEQ / 128, NSAMP), 256, GEMM_SMEM>>>(
        p_x1, Wgu, p_gu, SEQ, 2 * INTER, DM, DM, 2 * INTER, 2 * INTER,
        1, (long long)SEQ * DM, 0, 0, 0,
        (long long)SEQ * 2 * INTER, 0,
        1, (long long)DM * 2 * INTER, 1.0f);

    // act = silu(gate) * up
    act_kernel<<<(NSAMP * SEQ * INTER) / 256, 256>>>();

    // mlp = act @ Wd[e]
    mma_gemm<128, 128, 2, 4, false><<<dim3(DM / 128, SEQ / 128, NSAMP), 256, GEMM_SMEM>>>(
        p_act, Wd, p_mlp, SEQ, DM, INTER, INTER, DM, DM,
        1, (long long)SEQ * INTER, 0, 0, 0,
        (long long)SEQ * DM, 0,
        1, (long long)INTER * DM, 1.0f);

    // out = sum of weighted rmsnorm(x1 + mlp)
    final_kernel<<<BATCH * SEQ, 256>>>(out);
}

// round 6
// speedup vs baseline: 4.0414x; 1.0992x over previous
#include <cuda_runtime.h>
#include <math.h>
#include <stdint.h>

#define SEQ   1024
#define DM    1024
#define HN    16
#define HDIM  64
#define NSAMP 8
#define INTER 768
#define BATCH 4
#define EPS   1e-5f

// ---------------- scratch (device globals; no allocations allowed) ----------
__device__ float g_hsmean[BATCH * DM];
__device__ float g_partial[BATCH * 16 * DM];
__device__ int   g_expert[NSAMP];
__device__ float g_w[NSAMP];
__device__ float g_qkv[(size_t)NSAMP * SEQ * 3 * DM];        // 96 MB
__device__ float g_ctx[(size_t)NSAMP * SEQ * DM];            // 32 MB
__device__ float g_ao[(size_t)NSAMP * SEQ * DM];             // 32 MB
__device__ float g_x1[(size_t)NSAMP * SEQ * DM];             // 32 MB
__device__ float g_gu[(size_t)NSAMP * SEQ * 2 * INTER];      // 48 MB
__device__ float g_act[(size_t)NSAMP * SEQ * INTER];         // 24 MB
__device__ float g_mlp[(size_t)NSAMP * SEQ * DM];            // 32 MB

// ---------------- small helpers ----------------------------------------------
__device__ __forceinline__ float block_reduce_sum(float v, float* sh) {
    int tid = threadIdx.x;
    #pragma unroll
    for (int o = 16; o; o >>= 1) v += __shfl_down_sync(0xFFFFFFFFu, v, o);
    if ((tid & 31) == 0) sh[tid >> 5] = v;
    __syncthreads();
    float r = 0.f;
    if (tid < 32) {
        float x = (tid < (int)(blockDim.x >> 5)) ? sh[tid] : 0.f;
        #pragma unroll
        for (int o = 16; o; o >>= 1) x += __shfl_down_sync(0xFFFFFFFFu, x, o);
        if (tid == 0) sh[0] = x;
    }
    __syncthreads();
    r = sh[0];
    __syncthreads();
    return r;
}

__device__ __forceinline__ void mma_tf32(float* d, const uint32_t* a, const uint32_t* b) {
    asm volatile(
        "mma.sync.aligned.m16n8k8.row.col.f32.tf32.tf32.f32 "
        "{%0,%1,%2,%3},{%4,%5,%6,%7},{%8,%9},{%0,%1,%2,%3};"
        : "+f"(d[0]), "+f"(d[1]), "+f"(d[2]), "+f"(d[3])
        : "r"(a[0]), "r"(a[1]), "r"(a[2]), "r"(a[3]), "r"(b[0]), "r"(b[1]));
}

__device__ __forceinline__ void ldsm_x4(uint32_t* r, uint32_t addr) {
    asm volatile(
        "ldmatrix.sync.aligned.m8n8.x4.shared.b16 {%0,%1,%2,%3}, [%4];"
        : "=r"(r[0]), "=r"(r[1]), "=r"(r[2]), "=r"(r[3]) : "r"(addr));
}

__device__ __forceinline__ void cp16(uint32_t s, const void* g) {
    asm volatile("cp.async.cg.shared.global [%0], [%1], 16;" :: "r"(s), "l"(g));
}
__device__ __forceinline__ void cp_commit() {
    asm volatile("cp.async.commit_group;" ::: "memory");
}
__device__ __forceinline__ void cp_wait0() {
    asm volatile("cp.async.wait_group 0;" ::: "memory");
}
__device__ __forceinline__ void cp_wait1() {
    asm volatile("cp.async.wait_group 1;" ::: "memory");
}

// ---------------- routing ----------------------------------------------------
__global__ void mean1_kernel(const float* __restrict__ hidden) {
    int b = blockIdx.x, c = blockIdx.y;
    int tid = threadIdx.x;
    float acc[4] = {0.f, 0.f, 0.f, 0.f};
    for (int s = c * 64; s < c * 64 + 64; s++) {
        const float* row = hidden + ((size_t)b * SEQ + s) * DM;
        #pragma unroll
        for (int i = 0; i < 4; i++) acc[i] += row[tid + i * 256];
    }
    #pragma unroll
    for (int i = 0; i < 4; i++)
        g_partial[((size_t)b * 16 + c) * DM + tid + i * 256] = acc[i];
}

__global__ void mean2_kernel() {
    int b = blockIdx.x;
    int tid = threadIdx.x;
    #pragma unroll
    for (int i = 0; i < 4; i++) {
        int d = tid + i * 256;
        float s = 0.f;
        for (int c = 0; c < 16; c++) s += g_partial[((size_t)b * 16 + c) * DM + d];
        g_hsmean[b * DM + d] = s * (1.0f / (float)SEQ);
    }
}

__global__ void routing_kernel(const float* __restrict__ Wr,
                               const float* __restrict__ temperature,
                               float* __restrict__ out_logits) {
    int tid = threadIdx.x;          // 1024
    int w = tid >> 5, lane = tid & 31;
    int b = w >> 3, c = w & 7;
    float s = 0.f;
    for (int d = lane; d < DM; d += 32)
        s += g_hsmean[b * DM + d] * Wr[c * DM + d];
    #pragma unroll
    for (int o = 16; o; o >>= 1) s += __shfl_down_sync(0xFFFFFFFFu, s, o);
    __shared__ float logits[32];
    if (lane == 0) logits[w] = s;
    __syncthreads();
    if (tid < BATCH) {
        float t = fminf(fmaxf(temperature[0], 0.1f), 10.0f);
        float lv[8];
        #pragma unroll
        for (int cc = 0; cc < 8; cc++) {
            lv[cc] = logits[tid * 8 + cc] / t;
            out_logits[tid * 8 + cc] = lv[cc];
        }
        int i0 = 0;
        #pragma unroll
        for (int cc = 1; cc < 8; cc++) if (lv[cc] > lv[i0]) i0 = cc;
        int i1 = -1;
        #pragma unroll
        for (int cc = 0; cc < 8; cc++) {
            if (cc == i0) continue;
            if (i1 < 0 || lv[cc] > lv[i1]) i1 = cc;
        }
        float e = expf(lv[i1] - lv[i0]);
        g_expert[2 * tid]     = i0;
        g_expert[2 * tid + 1] = i1;
        g_w[2 * tid]     = 1.0f / (1.0f + e);
        g_w[2 * tid + 1] = e / (1.0f + e);
    }
}

// ---------------- tf32 tensor-core GEMM v3 ------------------------------------
// BK=32, 3-stage cp.async, ldmatrix A fragments, ks-pipelined register frags.
#define BM_  128
#define BN_  128
#define BK_  32
#define ASTR_ 36
#define BSTR_ 136
#define ASZ_ (BM_ * ASTR_)
#define BSZ_ (BK_ * BSTR_)
#define GEMM_SMEM (3 * (ASZ_ + BSZ_) * 4)

__global__ __launch_bounds__(256) void mma_gemm(
    const float* __restrict__ Ab, const float* __restrict__ Bb, float* __restrict__ Cb,
    int N, int K, int lda,
    long long strideA, int a_div2, long long strideC, long long sbExp)
{
    extern __shared__ float dynsm[];
    float* sA = dynsm;                 // 3 x ASZ_
    float* sB = dynsm + 3 * ASZ_;      // 3 x BSZ_

    int z = blockIdx.z;
    const float* A = Ab + (size_t)(a_div2 ? (z >> 1) : z) * strideA;
    const float* B = Bb + (long long)g_expert[z] * sbExp;
    float* C = Cb + (size_t)z * strideC;

    int row0 = blockIdx.y * BM_;
    int n0   = blockIdx.x * BN_;
    int tid = threadIdx.x, lane = tid & 31, wid = tid >> 5;
    int wm0 = (wid & 1) * 64;          // 2 x 4 warp grid, warp tile 64x32
    int wn0 = (wid >> 1) * 32;
    int g = lane >> 2, t = lane & 3;

    uint32_t sAu = (uint32_t)__cvta_generic_to_shared(sA);
    uint32_t sBu = (uint32_t)__cvta_generic_to_shared(sB);

    // per-thread ldsm base: row = wm0 + (lane&15), col-chunk = (lane>>4)*4 floats
    uint32_t aFragOff = (uint32_t)(((wm0 + (lane & 15)) * ASTR_ + (lane >> 4) * 4) * 4);

    float acc[4][4][4];
    #pragma unroll
    for (int i = 0; i < 4; i++)
        #pragma unroll
        for (int j = 0; j < 4; j++)
            #pragma unroll
            for (int q = 0; q < 4; q++) acc[i][j][q] = 0.f;

    auto load_tile = [&](int k0, int buf) {
        #pragma unroll
        for (int p = 0; p < 4; p++) {
            int i = tid + p * 256;
            int m = i >> 3, kc = (i & 7) * 4;
            cp16(sAu + (uint32_t)(buf * ASZ_ + m * ASTR_ + kc) * 4,
                 A + (size_t)(row0 + m) * lda + k0 + kc);
        }
        #pragma unroll
        for (int p = 0; p < 4; p++) {
            int i = tid + p * 256;
            int kr = i >> 5, nc = (i & 31) * 4;
            cp16(sBu + (uint32_t)(buf * BSZ_ + kr * BSTR_ + nc) * 4,
                 B + (size_t)(k0 + kr) * N + n0 + nc);
        }
    };

    int NT = K / BK_;
    load_tile(0, 0);
    cp_commit();
    load_tile(BK_, 1);
    cp_commit();

    uint32_t af[2][4][4];
    uint32_t bf[2][4][2];

    int buf = 0;
    for (int tI = 0; tI < NT; ++tI) {
        if (tI + 1 < NT) cp_wait1(); else cp_wait0();
        __syncthreads();
        if (tI + 2 < NT) {
            int nb = buf + 2; if (nb >= 3) nb -= 3;
            load_tile((tI + 2) * BK_, nb);
            cp_commit();
        }
        uint32_t aBase = sAu + (uint32_t)(buf * ASZ_) * 4 + aFragOff;
        const float* bTile = sB + buf * BSZ_;

        // ks = 0 fragments
        #pragma unroll
        for (int i = 0; i < 4; i++)
            ldsm_x4(af[0][i], aBase + (uint32_t)(i * 16 * ASTR_) * 4);
        #pragma unroll
        for (int j = 0; j < 4; j++) {
            int n = wn0 + j * 8 + g;
            bf[0][j][0] = __float_as_uint(bTile[t * BSTR_ + n]);
            bf[0][j][1] = __float_as_uint(bTile[(t + 4) * BSTR_ + n]);
        }

        #pragma unroll
        for (int ks = 0; ks < 4; ks++) {
            int cb = ks & 1, nb = cb ^ 1;
            if (ks < 3) {
                uint32_t kOff = (uint32_t)((ks + 1) * 8 * 4);
                #pragma unroll
                for (int i = 0; i < 4; i++)
                    ldsm_x4(af[nb][i], aBase + (uint32_t)(i * 16 * ASTR_) * 4 + kOff);
                #pragma unroll
                for (int j = 0; j < 4; j++) {
                    int n = wn0 + j * 8 + g;
                    bf[nb][j][0] = __float_as_uint(bTile[((ks + 1) * 8 + t) * BSTR_ + n]);
                    bf[nb][j][1] = __float_as_uint(bTile[((ks + 1) * 8 + t + 4) * BSTR_ + n]);
                }
            }
            #pragma unroll
            for (int i = 0; i < 4; i++)
                #pragma unroll
                for (int j = 0; j < 4; j++)
                    mma_tf32(acc[i][j], af[cb][i], bf[cb][j]);
        }
        buf++; if (buf == 3) buf = 0;
    }

    #pragma unroll
    for (int i = 0; i < 4; i++) {
        #pragma unroll
        for (int j = 0; j < 4; j++) {
            int r = row0 + wm0 + i * 16 + g;
            int c = n0 + wn0 + j * 8 + t * 2;
            *(float2*)(C + (size_t)r * N + c) = make_float2(acc[i][j][0], acc[i][j][1]);
            *(float2*)(C + (size_t)(r + 8) * N + c) = make_float2(acc[i][j][2], acc[i][j][3]);
        }
    }
}

// ---------------- RoPE (in-place on q,k inside g_qkv) ------------------------
__global__ void rope_kernel(const float* __restrict__ cosb, const float* __restrict__ sinb) {
    int s = blockIdx.x, n = blockIdx.y;
    int tid = threadIdx.x;            // 512
    int h = tid >> 5, j = tid & 31;
    float c0 = cosb[s * HDIM + j],      s0 = sinb[s * HDIM + j];
    float c1 = cosb[s * HDIM + j + 32], s1 = sinb[s * HDIM + j + 32];
    float* row = g_qkv + ((size_t)n * SEQ + s) * (3 * DM);
    float* q = row + h * HDIM;
    float qa = q[j], qb = q[j + 32];
    q[j]      = qa * c0 - qb * s0;
    q[j + 32] = qb * c1 + qa * s1;
    float* k = row + DM + h * HDIM;
    float ka = k[j], kb = k[j + 32];
    k[j]      = ka * c0 - kb * s0;
    k[j + 32] = kb * c1 + ka * s1;
}

// ---------------- flash attention: QK^T -> online softmax -> P@V -------------
#define QSTR 68
#define KSTR 68
#define VSTR 72
#define FLASH_SMEM ((64 * QSTR + 2 * 64 * KSTR + 2 * 64 * VSTR) * 4)

__global__ __launch_bounds__(128) void flash_kernel() {
    extern __shared__ float sm[];
    float* Qs = sm;
    float* Ks = sm + 64 * QSTR;
    float* Vs = sm + 64 * QSTR + 2 * 64 * KSTR;

    int nh = blockIdx.y;
    int n = nh >> 4, h = nh & 15;
    int q0 = blockIdx.x * 64;
    const float* qbase = g_qkv + (size_t)n * SEQ * (3 * DM) + h * HDIM;
    const float* kbase = qbase + DM;
    const float* vbase = qbase + 2 * DM;

    int tid = threadIdx.x, lane = tid & 31, wid = tid >> 5;
    int g = lane >> 2, t = lane & 3;
    int wm0 = wid * 16;

    uint32_t su = (uint32_t)__cvta_generic_to_shared(sm);
    uint32_t qsu = su;
    uint32_t ksu = su + 64 * QSTR * 4;
    uint32_t vsu = su + (64 * QSTR + 2 * 64 * KSTR) * 4;

    #pragma unroll
    for (int p = 0; p < 8; p++) {
        int i = tid + p * 128;
        int row = i >> 4, c4 = (i & 15) * 4;
        cp16(qsu + (uint32_t)(row * QSTR + c4) * 4,
             qbase + (size_t)(q0 + row) * (3 * DM) + c4);
        cp16(ksu + (uint32_t)(row * KSTR + c4) * 4,
             kbase + (size_t)row * (3 * DM) + c4);
        cp16(vsu + (uint32_t)(row * VSTR + c4) * 4,
             vbase + (size_t)row * (3 * DM) + c4);
    }
    cp_commit();
    cp_wait0();
    __syncthreads();

    uint32_t qf[8][4];
    #pragma unroll
    for (int kc = 0; kc < 8; kc++) {
        int r = wm0 + g;
        qf[kc][0] = __float_as_uint(Qs[r * QSTR + kc * 8 + t]);
        qf[kc][1] = __float_as_uint(Qs[(r + 8) * QSTR + kc * 8 + t]);
        qf[kc][2] = __float_as_uint(Qs[r * QSTR + kc * 8 + t + 4]);
        qf[kc][3] = __float_as_uint(Qs[(r + 8) * QSTR + kc * 8 + t + 4]);
    }

    float m0 = -INFINITY, m1 = -INFINITY, l0 = 0.f, l1 = 0.f;
    float oa[8][4];
    #pragma unroll
    for (int j = 0; j < 8; j++)
        #pragma unroll
        for (int q = 0; q < 4; q++) oa[j][q] = 0.f;

    const int NT = SEQ / 64;
    for (int it = 0; it < NT; it++) {
        int buf = it & 1;
        if (it + 1 < NT) {
            int kv = (it + 1) * 64;
            int ob = buf ^ 1;
            #pragma unroll
            for (int p = 0; p < 8; p++) {
                int i = tid + p * 128;
                int row = i >> 4, c4 = (i & 15) * 4;
                cp16(ksu + (uint32_t)(ob * 64 * KSTR + row * KSTR + c4) * 4,
                     kbase + (size_t)(kv + row) * (3 * DM) + c4);
                cp16(vsu + (uint32_t)(ob * 64 * VSTR + row * VSTR + c4) * 4,
                     vbase + (size_t)(kv + row) * (3 * DM) + c4);
            }
            cp_commit();
        }
        const float* kb = Ks + buf * 64 * KSTR;
        const float* vb = Vs + buf * 64 * VSTR;

        float sacc[8][4];
        #pragma unroll
        for (int j = 0; j < 8; j++)
            #pragma unroll
            for (int q = 0; q < 4; q++) sacc[j][q] = 0.f;

        #pragma unroll
        for (int kc = 0; kc < 8; kc++) {
            #pragma unroll
            for (int nt = 0; nt < 8; nt++) {
                uint32_t bfv[2];
                int nrow = nt * 8 + g;
                bfv[0] = __float_as_uint(kb[nrow * KSTR + kc * 8 + t]);
                bfv[1] = __float_as_uint(kb[nrow * KSTR + kc * 8 + t + 4]);
                mma_tf32(sacc[nt], qf[kc], bfv);
            }
        }

        float rm0 = -INFINITY, rm1 = -INFINITY;
        #pragma unroll
        for (int nt = 0; nt < 8; nt++) {
            #pragma unroll
            for (int q = 0; q < 4; q++) sacc[nt][q] *= 0.125f;
            rm0 = fmaxf(rm0, fmaxf(sacc[nt][0], sacc[nt][1]));
            rm1 = fmaxf(rm1, fmaxf(sacc[nt][2], sacc[nt][3]));
        }
        rm0 = fmaxf(rm0, __shfl_xor_sync(0xFFFFFFFFu, rm0, 1));
        rm0 = fmaxf(rm0, __shfl_xor_sync(0xFFFFFFFFu, rm0, 2));
        rm1 = fmaxf(rm1, __shfl_xor_sync(0xFFFFFFFFu, rm1, 1));
        rm1 = fmaxf(rm1, __shfl_xor_sync(0xFFFFFFFFu, rm1, 2));
        float mn0 = fmaxf(m0, rm0), mn1 = fmaxf(m1, rm1);
        float c0 = __expf(m0 - mn0), c1 = __expf(m1 - mn1);
        float ls0 = 0.f, ls1 = 0.f;
        #pragma unroll
        for (int nt = 0; nt < 8; nt++) {
            sacc[nt][0] = __expf(sacc[nt][0] - mn0);
            sacc[nt][1] = __expf(sacc[nt][1] - mn0);
            sacc[nt][2] = __expf(sacc[nt][2] - mn1);
            sacc[nt][3] = __expf(sacc[nt][3] - mn1);
            ls0 += sacc[nt][0] + sacc[nt][1];
            ls1 += sacc[nt][2] + sacc[nt][3];
        }
        ls0 += __shfl_xor_sync(0xFFFFFFFFu, ls0, 1);
        ls0 += __shfl_xor_sync(0xFFFFFFFFu, ls0, 2);
        ls1 += __shfl_xor_sync(0xFFFFFFFFu, ls1, 1);
        ls1 += __shfl_xor_sync(0xFFFFFFFFu, ls1, 2);
        l0 = l0 * c0 + ls0;
        l1 = l1 * c1 + ls1;
        m0 = mn0; m1 = mn1;
        #pragma unroll
        for (int j = 0; j < 8; j++) {
            oa[j][0] *= c0; oa[j][1] *= c0;
            oa[j][2] *= c1; oa[j][3] *= c1;
        }

        int srcA = (lane & ~3) | (t >> 1);
        int srcB = srcA + 2;
        bool odd = (t & 1);
        #pragma unroll
        for (int kc = 0; kc < 8; kc++) {
            float u0 = __shfl_sync(0xFFFFFFFFu, sacc[kc][0], srcA);
            float u1 = __shfl_sync(0xFFFFFFFFu, sacc[kc][1], srcA);
            float w0 = __shfl_sync(0xFFFFFFFFu, sacc[kc][0], srcB);
            float w1 = __shfl_sync(0xFFFFFFFFu, sacc[kc][1], srcB);
            float v0 = __shfl_sync(0xFFFFFFFFu, sacc[kc][2], srcA);
            float v1 = __shfl_sync(0xFFFFFFFFu, sacc[kc][3], srcA);
            float x0 = __shfl_sync(0xFFFFFFFFu, sacc[kc][2], srcB);
            float x1 = __shfl_sync(0xFFFFFFFFu, sacc[kc][3], srcB);
            uint32_t afv[4];
            afv[0] = __float_as_uint(odd ? u1 : u0);
            afv[1] = __float_as_uint(odd ? v1 : v0);
            afv[2] = __float_as_uint(odd ? w1 : w0);
            afv[3] = __float_as_uint(odd ? x1 : x0);
            #pragma unroll
            for (int jn = 0; jn < 8; jn++) {
                uint32_t bfv[2];
                bfv[0] = __float_as_uint(vb[(kc * 8 + t) * VSTR + jn * 8 + g]);
                bfv[1] = __float_as_uint(vb[(kc * 8 + t + 4) * VSTR + jn * 8 + g]);
                mma_tf32(oa[jn], afv, bfv);
            }
        }

        cp_wait0();
        __syncthreads();
    }

    float inv0 = 1.0f / l0, inv1 = 1.0f / l1;
    int grow0 = q0 + wm0 + g;
    float* cbase = g_ctx + (size_t)n * SEQ * DM + h * HDIM;
    #pragma unroll
    for (int jn = 0; jn < 8; jn++) {
        int col = jn * 8 + 2 * t;
        *(float2*)(cbase + (size_t)grow0 * DM + col) =
            make_float2(oa[jn][0] * inv0, oa[jn][1] * inv0);
        *(float2*)(cbase + (size_t)(grow0 + 8) * DM + col) =
            make_float2(oa[jn][2] * inv1, oa[jn][3] * inv1);
    }
}

// ---------------- residual + rmsnorm ------------------------------------------
__global__ void resid_rms_kernel(const float* __restrict__ hidden) {
    __shared__ float sh[32];
    int ns = blockIdx.x;
    int n = ns >> 10, s = ns & 1023;
    const float* xr = hidden + ((size_t)(n >> 1) * SEQ + s) * DM;
    const float* ar = g_ao + ((size_t)n * SEQ + s) * DM;
    float* o = g_x1 + ((size_t)n * SEQ + s) * DM;
    int tid = threadIdx.x;
    float y[4];
    float ss = 0.f;
    #pragma unroll
    for (int i = 0; i < 4; i++) {
        int d = tid + i * 256;
        y[i] = xr[d] + ar[d];
        ss = fmaf(y[i], y[i], ss);
    }
    ss = block_reduce_sum(ss, sh);
    float scale = rsqrtf(ss * (1.0f / (float)DM) + EPS);
    #pragma unroll
    for (int i = 0; i < 4; i++) o[tid + i * 256] = y[i] * scale;
}

// ---------------- silu(gate) * up ----------------------------------------------
__global__ void act_kernel() {
    size_t idx = (size_t)blockIdx.x * blockDim.x + threadIdx.x;
    size_t r = idx / INTER;
    int i = (int)(idx % INTER);
    float g = g_gu[r * (2 * INTER) + i];
    float u = g_gu[r * (2 * INTER) + INTER + i];
    float sg = g / (1.0f + __expf(-g));
    g_act[idx] = sg * u;
}

// ---------------- final: rmsnorm(x1 + mlp), weighted top-2 combine -------------
__global__ void final_kernel(float* __restrict__ out) {
    __shared__ float sh[32];
    int bs = blockIdx.x;
    int b = bs >> 10, s = bs & 1023;
    int tid = threadIdx.x;
    int n0 = 2 * b, n1 = 2 * b + 1;
    size_t base0 = ((size_t)n0 * SEQ + s) * DM;
    size_t base1 = ((size_t)n1 * SEQ + s) * DM;
    float y0[4], y1[4];
    float ss0 = 0.f, ss1 = 0.f;
    #pragma unroll
    for (int i = 0; i < 4; i++) {
        int d = tid + i * 256;
        y0[i] = g_x1[base0 + d] + g_mlp[base0 + d];
        y1[i] = g_x1[base1 + d] + g_mlp[base1 + d];
        ss0 = fmaf(y0[i], y0[i], ss0);
        ss1 = fmaf(y1[i], y1[i], ss1);
    }
    ss0 = block_reduce_sum(ss0, sh);
    ss1 = block_reduce_sum(ss1, sh);
    float r0 = rsqrtf(ss0 * (1.0f / (float)DM) + EPS) * g_w[n0];
    float r1 = rsqrtf(ss1 * (1.0f / (float)DM) + EPS) * g_w[n1];
    float* orow = out + ((size_t)b * SEQ + s) * DM;
    #pragma unroll
    for (int i = 0; i < 4; i++) {
        int d = tid + i * 256;
        orow[d] = y0[i] * r0 + y1[i] * r1;
    }
}

// ---------------- host launcher --------------------------------------------------
extern "C" void kernel_launch(void* const* d_in, const int* in_sizes, int n_in,
                              void* d_out, int out_size) {
    const float* hidden = (const float*)d_in[0];
    const float* cosb   = (const float*)d_in[1];
    const float* sinb   = (const float*)d_in[2];
    const float* Wr     = (const float*)d_in[3];
    const float* temp   = (const float*)d_in[4];
    const float* Wqkv   = (const float*)d_in[5];
    const float* Wo     = (const float*)d_in[6];
    const float* Wgu    = (const float*)d_in[7];
    const float* Wd     = (const float*)d_in[8];
    float* out = (float*)d_out;

    float *p_qkv, *p_ctx, *p_ao, *p_x1, *p_gu, *p_act, *p_mlp;
    cudaGetSymbolAddress((void**)&p_qkv, g_qkv);
    cudaGetSymbolAddress((void**)&p_ctx, g_ctx);
    cudaGetSymbolAddress((void**)&p_ao,  g_ao);
    cudaGetSymbolAddress((void**)&p_x1,  g_x1);
    cudaGetSymbolAddress((void**)&p_gu,  g_gu);
    cudaGetSymbolAddress((void**)&p_act, g_act);
    cudaGetSymbolAddress((void**)&p_mlp, g_mlp);

    cudaFuncSetAttribute(flash_kernel,
                         cudaFuncAttributeMaxDynamicSharedMemorySize, FLASH_SMEM);
    cudaFuncSetAttribute(mma_gemm,
                         cudaFuncAttributeMaxDynamicSharedMemorySize, GEMM_SMEM);

    // routing
    mean1_kernel<<<dim3(BATCH, 16), 256>>>(hidden);
    mean2_kernel<<<BATCH, 256>>>();
    routing_kernel<<<1, 1024>>>(Wr, temp, out + (size_t)BATCH * SEQ * DM);

    // qkv = x @ Wqkv[e]   (M=1024, N=3072, K=1024)
    mma_gemm<<<dim3(3072 / BN_, SEQ / BM_, NSAMP), 256, GEMM_SMEM>>>(
        hidden, Wqkv, p_qkv, 3 * DM, DM, DM,
        (long long)SEQ * DM, 1, (long long)SEQ * 3 * DM, (long long)DM * 3 * DM);

    // rope in-place
    rope_kernel<<<dim3(SEQ, NSAMP), 512>>>(cosb, sinb);

    // fused attention -> g_ctx
    flash_kernel<<<dim3(SEQ / 64, NSAMP * HN), 128, FLASH_SMEM>>>();

    // attn_out = ctx @ Wo[e]
    mma_gemm<<<dim3(DM / BN_, SEQ / BM_, NSAMP), 256, GEMM_SMEM>>>(
        p_ctx, Wo, p_ao, DM, DM, DM,
        (long long)SEQ * DM, 0, (long long)SEQ * DM, (long long)DM * DM);

    // x1 = rmsnorm(x + attn_out)
    resid_rms_kernel<<<NSAMP * SEQ, 256>>>(hidden);

    // gu = x1 @ Wgu[e]
    mma_gemm<<<dim3(2 * INTER / BN_, SEQ / BM_, NSAMP), 256, GEMM_SMEM>>>(
        p_x1, Wgu, p_gu, 2 * INTER, DM, DM,
        (long long)SEQ * DM, 0, (long long)SEQ * 2 * INTER, (long long)DM * 2 * INTER);

    // act = silu(gate) * up
    act_kernel<<<(NSAMP * SEQ * INTER) / 256, 256>>>();

    // mlp = act @ Wd[e]
    mma_gemm<<<dim3(DM / BN_, SEQ / BM_, NSAMP), 256, GEMM_SMEM>>>(
        p_act, Wd, p_mlp, DM, INTER, INTER,
        (long long)SEQ * INTER, 0, (long long)SEQ * DM, (long long)INTER * DM);

    // out = sum of weighted rmsnorm(x1 + mlp)
    final_kernel<<<BATCH * SEQ, 256>>>(out);
}

// round 7
// speedup vs baseline: 6.6354x; 1.6418x over previous
#include <cuda_runtime.h>
#include <cuda_bf16.h>
#include <math.h>
#include <stdint.h>

#define SEQ   1024
#define DM    1024
#define HN    16
#define HDIM  64
#define NSAMP 8
#define INTER 768
#define BATCH 4
#define EPS   1e-5f

typedef __nv_bfloat16 bf16;

// ---------------- scratch (device globals; no allocations allowed) ----------
__device__ float g_hsmean[BATCH * DM];
__device__ float g_partial[BATCH * 16 * DM];
__device__ int   g_expert[NSAMP];
__device__ float g_w[NSAMP];
__device__ bf16  g_hb[(size_t)BATCH * SEQ * DM];             // hidden bf16
__device__ bf16  g_qkvb[(size_t)NSAMP * SEQ * 3 * DM];       // 48 MB
__device__ bf16  g_ctxb[(size_t)NSAMP * SEQ * DM];           // 16 MB
__device__ float g_ao[(size_t)NSAMP * SEQ * DM];             // 32 MB
__device__ float g_x1[(size_t)NSAMP * SEQ * DM];             // 32 MB
__device__ bf16  g_x1b[(size_t)NSAMP * SEQ * DM];            // 16 MB
__device__ float g_gu[(size_t)NSAMP * SEQ * 2 * INTER];      // 48 MB
__device__ bf16  g_actb[(size_t)NSAMP * SEQ * INTER];        // 12 MB
__device__ float g_mlp[(size_t)NSAMP * SEQ * DM];            // 32 MB
// all-expert bf16 weights
#define WB_QKV 0LL
#define WB_WO  25165824LL
#define WB_GU  33554432LL
#define WB_WD  46137344LL
#define WB_TOTAL 52428800LL
__device__ bf16 g_wb[WB_TOTAL];                              // 105 MB

// ---------------- small helpers ----------------------------------------------
__device__ __forceinline__ float block_reduce_sum(float v, float* sh) {
    int tid = threadIdx.x;
    #pragma unroll
    for (int o = 16; o; o >>= 1) v += __shfl_down_sync(0xFFFFFFFFu, v, o);
    if ((tid & 31) == 0) sh[tid >> 5] = v;
    __syncthreads();
    float r = 0.f;
    if (tid < 32) {
        float x = (tid < (int)(blockDim.x >> 5)) ? sh[tid] : 0.f;
        #pragma unroll
        for (int o = 16; o; o >>= 1) x += __shfl_down_sync(0xFFFFFFFFu, x, o);
        if (tid == 0) sh[0] = x;
    }
    __syncthreads();
    r = sh[0];
    __syncthreads();
    return r;
}

__device__ __forceinline__ void mma_bf16(float* d, const uint32_t* a, const uint32_t* b) {
    asm volatile(
        "mma.sync.aligned.m16n8k16.row.col.f32.bf16.bf16.f32 "
        "{%0,%1,%2,%3},{%4,%5,%6,%7},{%8,%9},{%0,%1,%2,%3};"
        : "+f"(d[0]), "+f"(d[1]), "+f"(d[2]), "+f"(d[3])
        : "r"(a[0]), "r"(a[1]), "r"(a[2]), "r"(a[3]), "r"(b[0]), "r"(b[1]));
}

__device__ __forceinline__ void ldsm_x4(uint32_t* r, uint32_t addr) {
    asm volatile(
        "ldmatrix.sync.aligned.m8n8.x4.shared.b16 {%0,%1,%2,%3}, [%4];"
        : "=r"(r[0]), "=r"(r[1]), "=r"(r[2]), "=r"(r[3]) : "r"(addr));
}
__device__ __forceinline__ void ldsm_x2t(uint32_t* r, uint32_t addr) {
    asm volatile(
        "ldmatrix.sync.aligned.m8n8.x2.trans.shared.b16 {%0,%1}, [%2];"
        : "=r"(r[0]), "=r"(r[1]) : "r"(addr));
}
__device__ __forceinline__ uint32_t lds32(uint32_t a) {
    uint32_t v;
    asm volatile("ld.shared.b32 %0, [%1];" : "=r"(v) : "r"(a));
    return v;
}
__device__ __forceinline__ uint32_t packbf(float hi, float lo) {
    uint32_t r;
    asm("cvt.rn.bf16x2.f32 %0, %1, %2;" : "=r"(r) : "f"(hi), "f"(lo));
    return r;
}

__device__ __forceinline__ void cp16(uint32_t s, const void* g) {
    asm volatile("cp.async.cg.shared.global [%0], [%1], 16;" :: "r"(s), "l"(g));
}
__device__ __forceinline__ void cp_commit() {
    asm volatile("cp.async.commit_group;" ::: "memory");
}
__device__ __forceinline__ void cp_wait0() {
    asm volatile("cp.async.wait_group 0;" ::: "memory");
}
__device__ __forceinline__ void cp_wait1() {
    asm volatile("cp.async.wait_group 1;" ::: "memory");
}

// ---------------- fp32 -> bf16 conversion ------------------------------------
__global__ void cvt_bf16(const float4* __restrict__ s, uint2* __restrict__ d, int n4) {
    int i = blockIdx.x * blockDim.x + threadIdx.x;
    if (i < n4) {
        float4 v = s[i];
        uint2 o;
        o.x = packbf(v.y, v.x);
        o.y = packbf(v.w, v.z);
        d[i] = o;
    }
}

// ---------------- routing ----------------------------------------------------
__global__ void mean1_kernel(const float* __restrict__ hidden) {
    int b = blockIdx.x, c = blockIdx.y;
    int tid = threadIdx.x;
    float acc[4] = {0.f, 0.f, 0.f, 0.f};
    for (int s = c * 64; s < c * 64 + 64; s++) {
        const float* row = hidden + ((size_t)b * SEQ + s) * DM;
        #pragma unroll
        for (int i = 0; i < 4; i++) acc[i] += row[tid + i * 256];
    }
    #pragma unroll
    for (int i = 0; i < 4; i++)
        g_partial[((size_t)b * 16 + c) * DM + tid + i * 256] = acc[i];
}

__global__ void mean2_kernel() {
    int b = blockIdx.x;
    int tid = threadIdx.x;
    #pragma unroll
    for (int i = 0; i < 4; i++) {
        int d = tid + i * 256;
        float s = 0.f;
        for (int c = 0; c < 16; c++) s += g_partial[((size_t)b * 16 + c) * DM + d];
        g_hsmean[b * DM + d] = s * (1.0f / (float)SEQ);
    }
}

__global__ void routing_kernel(const float* __restrict__ Wr,
                               const float* __restrict__ temperature,
                               float* __restrict__ out_logits) {
    int tid = threadIdx.x;          // 1024
    int w = tid >> 5, lane = tid & 31;
    int b = w >> 3, c = w & 7;
    float s = 0.f;
    for (int d = lane; d < DM; d += 32)
        s += g_hsmean[b * DM + d] * Wr[c * DM + d];
    #pragma unroll
    for (int o = 16; o; o >>= 1) s += __shfl_down_sync(0xFFFFFFFFu, s, o);
    __shared__ float logits[32];
    if (lane == 0) logits[w] = s;
    __syncthreads();
    if (tid < BATCH) {
        float t = fminf(fmaxf(temperature[0], 0.1f), 10.0f);
        float lv[8];
        #pragma unroll
        for (int cc = 0; cc < 8; cc++) {
            lv[cc] = logits[tid * 8 + cc] / t;
            out_logits[tid * 8 + cc] = lv[cc];
        }
        int i0 = 0;
        #pragma unroll
        for (int cc = 1; cc < 8; cc++) if (lv[cc] > lv[i0]) i0 = cc;
        int i1 = -1;
        #pragma unroll
        for (int cc = 0; cc < 8; cc++) {
            if (cc == i0) continue;
            if (i1 < 0 || lv[cc] > lv[i1]) i1 = cc;
        }
        float e = expf(lv[i1] - lv[i0]);
        g_expert[2 * tid]     = i0;
        g_expert[2 * tid + 1] = i1;
        g_w[2 * tid]     = 1.0f / (1.0f + e);
        g_w[2 * tid + 1] = e / (1.0f + e);
    }
}

// ---------------- bf16 tensor-core GEMM ----------------------------------------
// BM=BN=128, BK=64, 3-stage cp.async, ldsm A (x4) + ldsm.trans B (x2).
#define ASTG 144                    // A row stride bytes (64 bf16 + 8 pad)
#define BSTG 272                    // B row stride bytes (128 bf16 + 8 pad)
#define ABYTES (128 * ASTG)         // 18432
#define BBYTES (64 * BSTG)          // 17408
#define STGB (ABYTES + BBYTES)      // 35840
#define GEMM_SMEM (3 * STGB)        // 107520

template<int OBF>
__global__ __launch_bounds__(256, 2) void gemm_bf(
    const bf16* __restrict__ Ab, const bf16* __restrict__ Bb, void* __restrict__ Cb,
    int N, int K, int lda, long long strideA, int a_div2, long long strideC)
{
    extern __shared__ char smraw[];
    uint32_t sb = (uint32_t)__cvta_generic_to_shared(smraw);
    int z = blockIdx.z;
    const bf16* A = Ab + (size_t)(a_div2 ? (z >> 1) : z) * strideA;
    const bf16* B = Bb + (long long)g_expert[z] * ((long long)K * N);
    int m0 = blockIdx.y * 128;
    int n0 = blockIdx.x * 128;
    int tid = threadIdx.x, lane = tid & 31, wid = tid >> 5;
    int wm0 = (wid & 1) * 64;       // warp tile 64x32
    int wn0 = (wid >> 1) * 32;
    int g = lane >> 2, t = lane & 3;

    auto load_tile = [&](int k0, int buf) {
        uint32_t base = sb + (uint32_t)(buf * STGB);
        #pragma unroll
        for (int p = 0; p < 4; p++) {
            int i = tid + p * 256;
            int row = i >> 3, ch = i & 7;
            cp16(base + (uint32_t)(row * ASTG + ch * 16),
                 A + (size_t)(m0 + row) * lda + k0 + ch * 8);
        }
        #pragma unroll
        for (int p = 0; p < 4; p++) {
            int i = tid + p * 256;
            int row = i >> 4, ch = i & 15;
            cp16(base + (uint32_t)(ABYTES + row * BSTG + ch * 16),
                 B + (size_t)(k0 + row) * N + n0 + ch * 8);
        }
    };

    int NT = K / 64;
    load_tile(0, 0);
    cp_commit();
    load_tile(64, 1);
    cp_commit();

    float acc[4][4][4];
    #pragma unroll
    for (int i = 0; i < 4; i++)
        #pragma unroll
        for (int j = 0; j < 4; j++)
            #pragma unroll
            for (int q = 0; q < 4; q++) acc[i][j][q] = 0.f;

    uint32_t af[2][4][4];
    uint32_t bfr[2][4][2];

    int buf = 0;
    for (int tI = 0; tI < NT; ++tI) {
        if (tI + 1 < NT) cp_wait1(); else cp_wait0();
        __syncthreads();
        if (tI + 2 < NT) {
            int nb = buf + 2; if (nb >= 3) nb -= 3;
            load_tile((tI + 2) * 64, nb);
            cp_commit();
        }
        uint32_t stage = sb + (uint32_t)(buf * STGB);
        uint32_t aB = stage + (uint32_t)((wm0 + (lane & 15)) * ASTG + (lane >> 4) * 16);
        uint32_t bB = stage + (uint32_t)(ABYTES + (lane & 15) * BSTG + wn0 * 2);

        #pragma unroll
        for (int i = 0; i < 4; i++) ldsm_x4(af[0][i], aB + (uint32_t)(i * 16 * ASTG));
        #pragma unroll
        for (int j = 0; j < 4; j++) ldsm_x2t(bfr[0][j], bB + (uint32_t)(j * 16));

        #pragma unroll
        for (int ks = 0; ks < 4; ks++) {
            int cb = ks & 1, nb2 = cb ^ 1;
            if (ks < 3) {
                #pragma unroll
                for (int i = 0; i < 4; i++)
                    ldsm_x4(af[nb2][i], aB + (uint32_t)(i * 16 * ASTG + (ks + 1) * 32));
                #pragma unroll
                for (int j = 0; j < 4; j++)
                    ldsm_x2t(bfr[nb2][j], bB + (uint32_t)((ks + 1) * 16 * BSTG + j * 16));
            }
            #pragma unroll
            for (int i = 0; i < 4; i++)
                #pragma unroll
                for (int j = 0; j < 4; j++)
                    mma_bf16(acc[i][j], af[cb][i], bfr[cb][j]);
        }
        buf++; if (buf == 3) buf = 0;
    }

    #pragma unroll
    for (int i = 0; i < 4; i++) {
        #pragma unroll
        for (int j = 0; j < 4; j++) {
            int r = m0 + wm0 + i * 16 + g;
            int c = n0 + wn0 + j * 8 + 2 * t;
            if (OBF) {
                bf16* C = (bf16*)Cb + (size_t)z * strideC;
                *(uint32_t*)(C + (size_t)r * N + c) = packbf(acc[i][j][1], acc[i][j][0]);
                *(uint32_t*)(C + (size_t)(r + 8) * N + c) = packbf(acc[i][j][3], acc[i][j][2]);
            } else {
                float* C = (float*)Cb + (size_t)z * strideC;
                *(float2*)(C + (size_t)r * N + c) = make_float2(acc[i][j][0], acc[i][j][1]);
                *(float2*)(C + (size_t)(r + 8) * N + c) = make_float2(acc[i][j][2], acc[i][j][3]);
            }
        }
    }
}

// ---------------- RoPE (in-place on bf16 q,k) ---------------------------------
__global__ void rope_kernel(const float* __restrict__ cosb, const float* __restrict__ sinb) {
    int s = blockIdx.x, n = blockIdx.y;
    int tid = threadIdx.x;            // 512
    int h = tid >> 5, j = tid & 31;
    float c0 = cosb[s * HDIM + j],      s0 = sinb[s * HDIM + j];
    float c1 = cosb[s * HDIM + j + 32], s1 = sinb[s * HDIM + j + 32];
    bf16* row = g_qkvb + ((size_t)n * SEQ + s) * (3 * DM);
    bf16* q = row + h * HDIM;
    float qa = __bfloat162float(q[j]), qb = __bfloat162float(q[j + 32]);
    q[j]      = __float2bfloat16(qa * c0 - qb * s0);
    q[j + 32] = __float2bfloat16(qb * c1 + qa * s1);
    bf16* k = row + DM + h * HDIM;
    float ka = __bfloat162float(k[j]), kb = __bfloat162float(k[j + 32]);
    k[j]      = __float2bfloat16(ka * c0 - kb * s0);
    k[j + 32] = __float2bfloat16(kb * c1 + ka * s1);
}

// ---------------- flash attention (bf16 mma) -----------------------------------
// smem: Q 64x(64+8) bf16, K/V double-buffered same shape. row stride 144B.
#define FQ 0
#define FK 9216
#define FV (9216 * 3)
#define FLASH_SMEM (9216 * 5)

__global__ __launch_bounds__(128) void flash_kernel() {
    extern __shared__ char smraw[];
    uint32_t sb = (uint32_t)__cvta_generic_to_shared(smraw);

    int nh = blockIdx.y;
    int n = nh >> 4, h = nh & 15;
    int q0 = blockIdx.x * 64;
    const bf16* qbase = g_qkvb + (size_t)n * SEQ * (3 * DM) + h * HDIM;
    const bf16* kbase = qbase + DM;
    const bf16* vbase = qbase + 2 * DM;

    int tid = threadIdx.x, lane = tid & 31, wid = tid >> 5;
    int g = lane >> 2, t = lane & 3;
    int wm0 = wid * 16;

    // initial loads: Q + K/V tile 0 (rows of 64 bf16 = 128B = 8 chunks)
    #pragma unroll
    for (int p = 0; p < 4; p++) {
        int i = tid + p * 128;
        int row = i >> 3, ch = i & 7;
        cp16(sb + (uint32_t)(FQ + row * 144 + ch * 16),
             qbase + (size_t)(q0 + row) * (3 * DM) + ch * 8);
        cp16(sb + (uint32_t)(FK + row * 144 + ch * 16),
             kbase + (size_t)row * (3 * DM) + ch * 8);
        cp16(sb + (uint32_t)(FV + row * 144 + ch * 16),
             vbase + (size_t)row * (3 * DM) + ch * 8);
    }
    cp_commit();
    cp_wait0();
    __syncthreads();

    // Q fragments: 4 k16 chunks
    uint32_t qf[4][4];
    uint32_t qA = sb + (uint32_t)(FQ + (wm0 + (lane & 15)) * 144 + (lane >> 4) * 16);
    #pragma unroll
    for (int kc = 0; kc < 4; kc++) ldsm_x4(qf[kc], qA + (uint32_t)(kc * 32));

    float m0 = -INFINITY, m1 = -INFINITY, l0 = 0.f, l1 = 0.f;
    float oa[8][4];
    #pragma unroll
    for (int j = 0; j < 8; j++)
        #pragma unroll
        for (int q = 0; q < 4; q++) oa[j][q] = 0.f;

    const int NT = SEQ / 64;
    for (int it = 0; it < NT; it++) {
        int buf = it & 1;
        if (it + 1 < NT) {
            int kv = (it + 1) * 64;
            int ob = buf ^ 1;
            #pragma unroll
            for (int p = 0; p < 4; p++) {
                int i = tid + p * 128;
                int row = i >> 3, ch = i & 7;
                cp16(sb + (uint32_t)(FK + ob * 9216 + row * 144 + ch * 16),
                     kbase + (size_t)(kv + row) * (3 * DM) + ch * 8);
                cp16(sb + (uint32_t)(FV + ob * 9216 + row * 144 + ch * 16),
                     vbase + (size_t)(kv + row) * (3 * DM) + ch * 8);
            }
            cp_commit();
        }
        uint32_t kB = sb + (uint32_t)(FK + buf * 9216);
        uint32_t vB = sb + (uint32_t)(FV + buf * 9216);

        // ---- S = Q K^T
        float sacc[8][4];
        #pragma unroll
        for (int j = 0; j < 8; j++)
            #pragma unroll
            for (int q = 0; q < 4; q++) sacc[j][q] = 0.f;

        #pragma unroll
        for (int kc = 0; kc < 4; kc++) {
            #pragma unroll
            for (int nt = 0; nt < 8; nt++) {
                uint32_t ba = kB + (uint32_t)((nt * 8 + g) * 144 + kc * 32 + t * 4);
                uint32_t bb[2];
                bb[0] = lds32(ba);
                bb[1] = lds32(ba + 16);
                mma_bf16(sacc[nt], qf[kc], bb);
            }
        }

        // ---- online softmax (scale 1/8)
        float rm0 = -INFINITY, rm1 = -INFINITY;
        #pragma unroll
        for (int nt = 0; nt < 8; nt++) {
            #pragma unroll
            for (int q = 0; q < 4; q++) sacc[nt][q] *= 0.125f;
            rm0 = fmaxf(rm0, fmaxf(sacc[nt][0], sacc[nt][1]));
            rm1 = fmaxf(rm1, fmaxf(sacc[nt][2], sacc[nt][3]));
        }
        rm0 = fmaxf(rm0, __shfl_xor_sync(0xFFFFFFFFu, rm0, 1));
        rm0 = fmaxf(rm0, __shfl_xor_sync(0xFFFFFFFFu, rm0, 2));
        rm1 = fmaxf(rm1, __shfl_xor_sync(0xFFFFFFFFu, rm1, 1));
        rm1 = fmaxf(rm1, __shfl_xor_sync(0xFFFFFFFFu, rm1, 2));
        float mn0 = fmaxf(m0, rm0), mn1 = fmaxf(m1, rm1);
        float c0 = __expf(m0 - mn0), c1 = __expf(m1 - mn1);
        float ls0 = 0.f, ls1 = 0.f;
        #pragma unroll
        for (int nt = 0; nt < 8; nt++) {
            sacc[nt][0] = __expf(sacc[nt][0] - mn0);
            sacc[nt][1] = __expf(sacc[nt][1] - mn0);
            sacc[nt][2] = __expf(sacc[nt][2] - mn1);
            sacc[nt][3] = __expf(sacc[nt][3] - mn1);
            ls0 += sacc[nt][0] + sacc[nt][1];
            ls1 += sacc[nt][2] + sacc[nt][3];
        }
        ls0 += __shfl_xor_sync(0xFFFFFFFFu, ls0, 1);
        ls0 += __shfl_xor_sync(0xFFFFFFFFu, ls0, 2);
        ls1 += __shfl_xor_sync(0xFFFFFFFFu, ls1, 1);
        ls1 += __shfl_xor_sync(0xFFFFFFFFu, ls1, 2);
        l0 = l0 * c0 + ls0;
        l1 = l1 * c1 + ls1;
        m0 = mn0; m1 = mn1;
        #pragma unroll
        for (int j = 0; j < 8; j++) {
            oa[j][0] *= c0; oa[j][1] *= c0;
            oa[j][2] *= c1; oa[j][3] *= c1;
        }

        // ---- O += P @ V  (P fragments are a direct repack — no shuffles)
        #pragma unroll
        for (int mC = 0; mC < 4; mC++) {
            uint32_t pa[4];
            pa[0] = packbf(sacc[2 * mC][1],     sacc[2 * mC][0]);
            pa[1] = packbf(sacc[2 * mC][3],     sacc[2 * mC][2]);
            pa[2] = packbf(sacc[2 * mC + 1][1], sacc[2 * mC + 1][0]);
            pa[3] = packbf(sacc[2 * mC + 1][3], sacc[2 * mC + 1][2]);
            #pragma unroll
            for (int jn = 0; jn < 8; jn++) {
                uint32_t vb[2];
                ldsm_x2t(vb, vB + (uint32_t)((mC * 16 + (lane & 15)) * 144 + jn * 16));
                mma_bf16(oa[jn], pa, vb);
            }
        }

        cp_wait0();
        __syncthreads();
    }

    float inv0 = 1.0f / l0, inv1 = 1.0f / l1;
    int grow0 = q0 + wm0 + g;
    bf16* cbase = g_ctxb + (size_t)n * SEQ * DM + h * HDIM;
    #pragma unroll
    for (int jn = 0; jn < 8; jn++) {
        int col = jn * 8 + 2 * t;
        *(uint32_t*)(cbase + (size_t)grow0 * DM + col) =
            packbf(oa[jn][1] * inv0, oa[jn][0] * inv0);
        *(uint32_t*)(cbase + (size_t)(grow0 + 8) * DM + col) =
            packbf(oa[jn][3] * inv1, oa[jn][2] * inv1);
    }
}

// ---------------- residual + rmsnorm (fp32 + bf16 outputs) ---------------------
__global__ void resid_rms_kernel(const float* __restrict__ hidden) {
    __shared__ float sh[32];
    int ns = blockIdx.x;
    int n = ns >> 10, s = ns & 1023;
    int tid = threadIdx.x;           // 256
    int d0 = tid * 4;
    size_t base = ((size_t)n * SEQ + s) * DM;
    float4 x4 = *(const float4*)(hidden + ((size_t)(n >> 1) * SEQ + s) * DM + d0);
    float4 a4 = *(const float4*)(g_ao + base + d0);
    float4 y = make_float4(x4.x + a4.x, x4.y + a4.y, x4.z + a4.z, x4.w + a4.w);
    float ss = y.x * y.x + y.y * y.y + y.z * y.z + y.w * y.w;
    ss = block_reduce_sum(ss, sh);
    float scale = rsqrtf(ss * (1.0f / (float)DM) + EPS);
    y.x *= scale; y.y *= scale; y.z *= scale; y.w *= scale;
    *(float4*)(g_x1 + base + d0) = y;
    uint2 o;
    o.x = packbf(y.y, y.x);
    o.y = packbf(y.w, y.z);
    *(uint2*)(g_x1b + base + d0) = o;
}

// ---------------- silu(gate) * up -> bf16 ---------------------------------------
__global__ void act_kernel() {
    int idx = blockIdx.x * blockDim.x + threadIdx.x;   // NSAMP*SEQ*INTER/2 threads
    size_t r = (size_t)idx / 384;
    int i2 = (idx % 384) * 2;
    float2 gv = *(const float2*)(g_gu + r * (2 * INTER) + i2);
    float2 uv = *(const float2*)(g_gu + r * (2 * INTER) + INTER + i2);
    float s0 = gv.x / (1.0f + __expf(-gv.x)) * uv.x;
    float s1 = gv.y / (1.0f + __expf(-gv.y)) * uv.y;
    *(uint32_t*)(g_actb + r * INTER + i2) = packbf(s1, s0);
}

// ---------------- final: rmsnorm(x1 + mlp), weighted top-2 combine -------------
__global__ void final_kernel(float* __restrict__ out) {
    __shared__ float sh[32];
    int bs = blockIdx.x;
    int b = bs >> 10, s = bs & 1023;
    int tid = threadIdx.x;
    int n0 = 2 * b, n1 = 2 * b + 1;
    size_t base0 = ((size_t)n0 * SEQ + s) * DM;
    size_t base1 = ((size_t)n1 * SEQ + s) * DM;
    float y0[4], y1[4];
    float ss0 = 0.f, ss1 = 0.f;
    #pragma unroll
    for (int i = 0; i < 4; i++) {
        int d = tid + i * 256;
        y0[i] = g_x1[base0 + d] + g_mlp[base0 + d];
        y1[i] = g_x1[base1 + d] + g_mlp[base1 + d];
        ss0 = fmaf(y0[i], y0[i], ss0);
        ss1 = fmaf(y1[i], y1[i], ss1);
    }
    ss0 = block_reduce_sum(ss0, sh);
    ss1 = block_reduce_sum(ss1, sh);
    float r0 = rsqrtf(ss0 * (1.0f / (float)DM) + EPS) * g_w[n0];
    float r1 = rsqrtf(ss1 * (1.0f / (float)DM) + EPS) * g_w[n1];
    float* orow = out + ((size_t)b * SEQ + s) * DM;
    #pragma unroll
    for (int i = 0; i < 4; i++) {
        int d = tid + i * 256;
        orow[d] = y0[i] * r0 + y1[i] * r1;
    }
}

// ---------------- host launcher --------------------------------------------------
extern "C" void kernel_launch(void* const* d_in, const int* in_sizes, int n_in,
                              void* d_out, int out_size) {
    const float* hidden = (const float*)d_in[0];
    const float* cosb   = (const float*)d_in[1];
    const float* sinb   = (const float*)d_in[2];
    const float* Wr     = (const float*)d_in[3];
    const float* temp   = (const float*)d_in[4];
    const float* Wqkv   = (const float*)d_in[5];
    const float* Wo     = (const float*)d_in[6];
    const float* Wgu    = (const float*)d_in[7];
    const float* Wd     = (const float*)d_in[8];
    float* out = (float*)d_out;

    bf16 *p_hb, *p_qkvb, *p_ctxb, *p_x1b, *p_actb, *p_wb;
    float *p_ao, *p_x1, *p_gu, *p_mlp;
    cudaGetSymbolAddress((void**)&p_hb,   g_hb);
    cudaGetSymbolAddress((void**)&p_qkvb, g_qkvb);
    cudaGetSymbolAddress((void**)&p_ctxb, g_ctxb);
    cudaGetSymbolAddress((void**)&p_x1b,  g_x1b);
    cudaGetSymbolAddress((void**)&p_actb, g_actb);
    cudaGetSymbolAddress((void**)&p_wb,   g_wb);
    cudaGetSymbolAddress((void**)&p_ao,   g_ao);
    cudaGetSymbolAddress((void**)&p_x1,   g_x1);
    cudaGetSymbolAddress((void**)&p_gu,   g_gu);
    cudaGetSymbolAddress((void**)&p_mlp,  g_mlp);

    cudaFuncSetAttribute(flash_kernel,
                         cudaFuncAttributeMaxDynamicSharedMemorySize, FLASH_SMEM);
    cudaFuncSetAttribute((const void*)gemm_bf<0>,
                         cudaFuncAttributeMaxDynamicSharedMemorySize, GEMM_SMEM);
    cudaFuncSetAttribute((const void*)gemm_bf<1>,
                         cudaFuncAttributeMaxDynamicSharedMemorySize, GEMM_SMEM);

    // bf16 conversions (routing-independent)
    {
        int n4;
        n4 = BATCH * SEQ * DM / 4;
        cvt_bf16<<<(n4 + 255) / 256, 256>>>((const float4*)hidden, (uint2*)p_hb, n4);
        n4 = 8 * DM * 3 * DM / 4;
        cvt_bf16<<<(n4 + 255) / 256, 256>>>((const float4*)Wqkv, (uint2*)(p_wb + WB_QKV), n4);
        n4 = 8 * DM * DM / 4;
        cvt_bf16<<<(n4 + 255) / 256, 256>>>((const float4*)Wo, (uint2*)(p_wb + WB_WO), n4);
        n4 = 8 * DM * 2 * INTER / 4;
        cvt_bf16<<<(n4 + 255) / 256, 256>>>((const float4*)Wgu, (uint2*)(p_wb + WB_GU), n4);
        n4 = 8 * INTER * DM / 4;
        cvt_bf16<<<(n4 + 255) / 256, 256>>>((const float4*)Wd, (uint2*)(p_wb + WB_WD), n4);
    }

    // routing
    mean1_kernel<<<dim3(BATCH, 16), 256>>>(hidden);
    mean2_kernel<<<BATCH, 256>>>();
    routing_kernel<<<1, 1024>>>(Wr, temp, out + (size_t)BATCH * SEQ * DM);

    // qkv = x @ Wqkv[e]   (bf16 out)
    gemm_bf<1><<<dim3(3072 / 128, 8, NSAMP), 256, GEMM_SMEM>>>(
        p_hb, p_wb + WB_QKV, p_qkvb, 3 * DM, DM, DM,
        (long long)SEQ * DM, 1, (long long)SEQ * 3 * DM);

    // rope in-place (bf16)
    rope_kernel<<<dim3(SEQ, NSAMP), 512>>>(cosb, sinb);

    // fused attention -> g_ctxb (bf16)
    flash_kernel<<<dim3(SEQ / 64, NSAMP * HN), 128, FLASH_SMEM>>>();

    // attn_out = ctx @ Wo[e]  (fp32 out)
    gemm_bf<0><<<dim3(DM / 128, 8, NSAMP), 256, GEMM_SMEM>>>(
        p_ctxb, p_wb + WB_WO, p_ao, DM, DM, DM,
        (long long)SEQ * DM, 0, (long long)SEQ * DM);

    // x1 = rmsnorm(x + attn_out)  (fp32 + bf16 outs)
    resid_rms_kernel<<<NSAMP * SEQ, 256>>>(hidden);

    // gu = x1 @ Wgu[e]  (fp32 out)
    gemm_bf<0><<<dim3(2 * INTER / 128, 8, NSAMP), 256, GEMM_SMEM>>>(
        p_x1b, p_wb + WB_GU, p_gu, 2 * INTER, DM, DM,
        (long long)SEQ * DM, 0, (long long)SEQ * 2 * INTER);

    // act = silu(gate) * up  (bf16 out)
    act_kernel<<<(NSAMP * SEQ * INTER / 2) / 256, 256>>>();

    // mlp = act @ Wd[e]  (fp32 out)
    gemm_bf<0><<<dim3(DM / 128, 8, NSAMP), 256, GEMM_SMEM>>>(
        p_actb, p_wb + WB_WD, p_mlp, DM, INTER, INTER,
        (long long)SEQ * INTER, 0, (long long)SEQ * DM);

    // out = sum of weighted rmsnorm(x1 + mlp)
    final_kernel<<<BATCH * SEQ, 256>>>(out);
}